// round 4
// baseline (speedup 1.0000x reference)
#include <cuda_runtime.h>
#include <cuda_bf16.h>
#include <math.h>

// Problem constants
#define BB 2
#define TT 2048
#define DM 1024
#define NH 16
#define DH 64
#define BT (BB*TT)          // 4096
#define BH (BB*NH)          // 32

// Scratch (device globals; no allocation allowed)
__device__ float g_q[BH * TT * DH];     // [B,H,T,Dh]
__device__ float g_k[BH * TT * DH];
__device__ float g_v[BH * TT * DH];
__device__ float g_attn[BT * DM];       // [B,T,D]

// ---------------------------------------------------------------------------
// GEMM: C[m,n] = sum_k A[m,k] * W[n,k] + bias[n]   (A row-major [M,1024],
// W row-major [1024,1024]).  MODE 0: fused QKV (N=3072, 3 weights, epilogue
// transposes to [B,H,T,Dh]).  MODE 1: output projection (N=1024 -> d_out).
// Tiles: BM=BN=128, BK=8, 256 threads, 8x8 per thread.
// ---------------------------------------------------------------------------
template <int MODE>
__global__ __launch_bounds__(256)
void gemm_nt_kernel(const float* __restrict__ A,
                    const float* __restrict__ Wq, const float* __restrict__ bq,
                    const float* __restrict__ Wk, const float* __restrict__ bk,
                    const float* __restrict__ Wv, const float* __restrict__ bv,
                    float* __restrict__ out)
{
    __shared__ float As[8][128];
    __shared__ float Bs[8][128];

    const int tid = threadIdx.x;
    const int bm  = blockIdx.y;
    const int bn  = blockIdx.x;
    const int n_base = bn * 128;

    const float* Ap = (MODE == 1) ? g_attn : A;

    // Select weight matrix for this N-tile (128 | 1024, so a tile never spans)
    const float* W;
    if (MODE == 0) {
        int w = n_base >> 10;
        W = (w == 0) ? Wq : (w == 1) ? Wk : Wv;
    } else {
        W = Wq;  // Wo passed via Wq slot
    }
    const int n_loc0 = (MODE == 0) ? (n_base & 1023) : n_base;

    const int ty = tid >> 4;        // 0..15
    const int tx = tid & 15;        // 0..15
    const int lrow = tid >> 1;      // 0..127 (load row within tile)
    const int lk4  = (tid & 1) * 4; // 0 or 4

    float acc[8][8];
    #pragma unroll
    for (int i = 0; i < 8; i++)
        #pragma unroll
        for (int j = 0; j < 8; j++) acc[i][j] = 0.0f;

    const float* aRow = Ap + (size_t)(bm * 128 + lrow) * 1024;
    const float* bRow = W  + (size_t)(n_loc0 + lrow) * 1024;

    for (int k0 = 0; k0 < 1024; k0 += 8) {
        float4 a4 = *(const float4*)(aRow + k0 + lk4);
        float4 b4 = *(const float4*)(bRow + k0 + lk4);
        As[lk4 + 0][lrow] = a4.x;  As[lk4 + 1][lrow] = a4.y;
        As[lk4 + 2][lrow] = a4.z;  As[lk4 + 3][lrow] = a4.w;
        Bs[lk4 + 0][lrow] = b4.x;  Bs[lk4 + 1][lrow] = b4.y;
        Bs[lk4 + 2][lrow] = b4.z;  Bs[lk4 + 3][lrow] = b4.w;
        __syncthreads();

        #pragma unroll
        for (int kk = 0; kk < 8; kk++) {
            float4 a0 = *(const float4*)&As[kk][ty * 8];
            float4 a1 = *(const float4*)&As[kk][ty * 8 + 4];
            float4 b0 = *(const float4*)&Bs[kk][tx * 8];
            float4 b1 = *(const float4*)&Bs[kk][tx * 8 + 4];
            float ar[8] = {a0.x, a0.y, a0.z, a0.w, a1.x, a1.y, a1.z, a1.w};
            float br[8] = {b0.x, b0.y, b0.z, b0.w, b1.x, b1.y, b1.z, b1.w};
            #pragma unroll
            for (int i = 0; i < 8; i++)
                #pragma unroll
                for (int j = 0; j < 8; j++)
                    acc[i][j] += ar[i] * br[j];
        }
        __syncthreads();
    }

    if (MODE == 0) {
        int w = n_base >> 10;
        const float* bias = (w == 0) ? bq : (w == 1) ? bk : bv;
        float* dst = (w == 0) ? g_q : (w == 1) ? g_k : g_v;
        #pragma unroll
        for (int i = 0; i < 8; i++) {
            int m  = bm * 128 + ty * 8 + i;
            int b_ = m >> 11;
            int t  = m & 2047;
            #pragma unroll
            for (int jj = 0; jj < 2; jj++) {
                int nl = n_loc0 + tx * 8 + jj * 4;
                int h  = nl >> 6;
                int dh = nl & 63;
                float4 r;
                r.x = acc[i][jj*4+0] + bias[nl+0];
                r.y = acc[i][jj*4+1] + bias[nl+1];
                r.z = acc[i][jj*4+2] + bias[nl+2];
                r.w = acc[i][jj*4+3] + bias[nl+3];
                *(float4*)&dst[(((size_t)(b_*NH + h) * TT) + t) * DH + dh] = r;
            }
        }
    } else {
        const float* bias = bq;  // bo passed via bq slot
        #pragma unroll
        for (int i = 0; i < 8; i++) {
            int m = bm * 128 + ty * 8 + i;
            #pragma unroll
            for (int jj = 0; jj < 2; jj++) {
                int n = n_base + tx * 8 + jj * 4;
                float4 r;
                r.x = acc[i][jj*4+0] + bias[n+0];
                r.y = acc[i][jj*4+1] + bias[n+1];
                r.z = acc[i][jj*4+2] + bias[n+2];
                r.w = acc[i][jj*4+3] + bias[n+3];
                *(float4*)&out[(size_t)m * DM + n] = r;
            }
        }
    }
}

// ---------------------------------------------------------------------------
// RoPE applied in-place to g_q and g_k.
// Mimics JAX fp32 rounding: arg = fp32(t) * fp32(inv_freq), rounded to fp32,
// then accurate cos/sin of that exact fp32 argument.
// ---------------------------------------------------------------------------
__global__ __launch_bounds__(256)
void rope_kernel()
{
    int idx = blockIdx.x * blockDim.x + threadIdx.x;
    const int total = BH * TT * 32;
    if (idx >= total) return;
    int i  = idx & 31;
    int t  = (idx >> 5) & 2047;
    int bh = idx >> 16;

    // inv_freq = 10000^(-2i/64) in fp32 (2i/64 is exact in fp32)
    double e   = -((double)(2 * i) / 64.0) * log(10000.0);
    float invf = (float)exp(e);
    float argf = (float)t * invf;         // fp32 rounding as in jnp.outer
    double arg = (double)argf;
    float c = (float)cos(arg);
    float s = (float)sin(arg);

    size_t base = ((size_t)bh * TT + t) * DH;
    float q1 = g_q[base + i], q2 = g_q[base + i + 32];
    g_q[base + i]      = q1 * c - q2 * s;
    g_q[base + i + 32] = q2 * c + q1 * s;
    float k1 = g_k[base + i], k2 = g_k[base + i + 32];
    g_k[base + i]      = k1 * c - k2 * s;
    g_k[base + i + 32] = k2 * c + k1 * s;
}

// ---------------------------------------------------------------------------
// Flash attention: one block per (bh, 64-query tile).  256 threads.
// Q pre-scaled by 1/sqrt(64).  Online softmax, half-warp shfl reductions.
// Smem = Qt(16K) + K/P shared buffer(16K) + V(16K) = 48KB.
// Output written directly in [B,T,D] layout into g_attn.
// ---------------------------------------------------------------------------
__global__ __launch_bounds__(256)
void attn_kernel()
{
    __shared__ float Qt[64][64];   // transposed: [d][r], pre-scaled
    __shared__ float KP[64][64];   // K transposed [d][c]; reused as P [r][c]
    __shared__ float Vs[64][64];   // natural: [c][d]

    const int bh = blockIdx.y;
    const int q0 = blockIdx.x * 64;
    const int tid = threadIdx.x;
    const int tx = tid & 15;       // dim group / col group
    const int ty = tid >> 4;       // row group

    const float* qptr  = g_q + ((size_t)bh * TT + q0) * DH;
    const float* kbase = g_k + (size_t)bh * TT * DH;
    const float* vbase = g_v + (size_t)bh * TT * DH;

    // Load Q tile, transposed + scaled.  4 threads per row, 4 float4s each
    // -> all 16 quads (64 floats) of the row are covered.
    {
        int row = tid >> 2, seg = tid & 3;
        #pragma unroll
        for (int rep = 0; rep < 4; rep++) {
            int c = (seg + rep * 4) * 4;          // 0,16,32,48 interleaved
            float4 v = *(const float4*)(qptr + row * 64 + c);
            Qt[c + 0][row] = v.x * 0.125f;
            Qt[c + 1][row] = v.y * 0.125f;
            Qt[c + 2][row] = v.z * 0.125f;
            Qt[c + 3][row] = v.w * 0.125f;
        }
    }

    float m_r[4], l_r[4], o[4][4];
    #pragma unroll
    for (int i = 0; i < 4; i++) {
        m_r[i] = -INFINITY; l_r[i] = 0.0f;
        #pragma unroll
        for (int j = 0; j < 4; j++) o[i][j] = 0.0f;
    }

    for (int j0 = 0; j0 < TT; j0 += 64) {
        // Load K (transposed) and V (natural) — full 64 dims per row
        {
            int row = tid >> 2, seg = tid & 3;
            const float* krow = kbase + (size_t)(j0 + row) * 64;
            const float* vrow = vbase + (size_t)(j0 + row) * 64;
            #pragma unroll
            for (int rep = 0; rep < 4; rep++) {
                int c = (seg + rep * 4) * 4;
                float4 kv = *(const float4*)(krow + c);
                KP[c + 0][row] = kv.x;
                KP[c + 1][row] = kv.y;
                KP[c + 2][row] = kv.z;
                KP[c + 3][row] = kv.w;
                float4 vv = *(const float4*)(vrow + c);
                *(float4*)&Vs[row][c] = vv;
            }
        }
        __syncthreads();

        // S = (Q*scale) K^T : 4x4 microtile per thread
        float s[4][4];
        #pragma unroll
        for (int i = 0; i < 4; i++)
            #pragma unroll
            for (int j = 0; j < 4; j++) s[i][j] = 0.0f;

        #pragma unroll 8
        for (int d = 0; d < 64; d++) {
            float4 qf = *(const float4*)&Qt[d][ty * 4];
            float4 kf = *(const float4*)&KP[d][tx * 4];
            float qa[4] = {qf.x, qf.y, qf.z, qf.w};
            float ka[4] = {kf.x, kf.y, kf.z, kf.w};
            #pragma unroll
            for (int i = 0; i < 4; i++)
                #pragma unroll
                for (int j = 0; j < 4; j++)
                    s[i][j] += qa[i] * ka[j];
        }

        // Online softmax per row (rows shared by 16-lane tx-groups)
        #pragma unroll
        for (int i = 0; i < 4; i++) {
            float mx = fmaxf(fmaxf(s[i][0], s[i][1]), fmaxf(s[i][2], s[i][3]));
            #pragma unroll
            for (int off = 1; off < 16; off <<= 1)
                mx = fmaxf(mx, __shfl_xor_sync(0xffffffffu, mx, off));
            float mnew = fmaxf(m_r[i], mx);
            float corr = __expf(m_r[i] - mnew);   // exp(-inf)=0 on first tile
            float rs = 0.0f;
            #pragma unroll
            for (int j = 0; j < 4; j++) {
                s[i][j] = __expf(s[i][j] - mnew);
                rs += s[i][j];
            }
            #pragma unroll
            for (int off = 1; off < 16; off <<= 1)
                rs += __shfl_xor_sync(0xffffffffu, rs, off);
            l_r[i] = l_r[i] * corr + rs;
            m_r[i] = mnew;
            #pragma unroll
            for (int j = 0; j < 4; j++) o[i][j] *= corr;
        }

        __syncthreads();   // done reading KP as K; safe to overwrite with P
        #pragma unroll
        for (int i = 0; i < 4; i++)
            *(float4*)&KP[ty * 4 + i][tx * 4] =
                make_float4(s[i][0], s[i][1], s[i][2], s[i][3]);
        __syncthreads();

        // O += P V
        #pragma unroll 8
        for (int c = 0; c < 64; c++) {
            float4 vf = *(const float4*)&Vs[c][tx * 4];
            float va[4] = {vf.x, vf.y, vf.z, vf.w};
            float p0 = KP[ty*4+0][c];
            float p1 = KP[ty*4+1][c];
            float p2 = KP[ty*4+2][c];
            float p3 = KP[ty*4+3][c];
            #pragma unroll
            for (int j = 0; j < 4; j++) {
                o[0][j] += p0 * va[j];
                o[1][j] += p1 * va[j];
                o[2][j] += p2 * va[j];
                o[3][j] += p3 * va[j];
            }
        }
        __syncthreads();   // before next K/V load
    }

    // Epilogue: normalize and write [B,T,D]
    const int b_ = bh >> 4, h = bh & 15;
    #pragma unroll
    for (int i = 0; i < 4; i++) {
        float inv = 1.0f / l_r[i];
        int t = q0 + ty * 4 + i;
        float4 r = make_float4(o[i][0]*inv, o[i][1]*inv, o[i][2]*inv, o[i][3]*inv);
        *(float4*)&g_attn[((size_t)(b_*TT + t)) * DM + h * DH + tx * 4] = r;
    }
}

// ---------------------------------------------------------------------------
extern "C" void kernel_launch(void* const* d_in, const int* in_sizes, int n_in,
                              void* d_out, int out_size)
{
    const float* x  = (const float*)d_in[0];
    const float* Wq = (const float*)d_in[1];
    const float* bq = (const float*)d_in[2];
    const float* Wk = (const float*)d_in[3];
    const float* bk = (const float*)d_in[4];
    const float* Wv = (const float*)d_in[5];
    const float* bv = (const float*)d_in[6];
    const float* Wo = (const float*)d_in[7];
    const float* bo = (const float*)d_in[8];
    float* out = (float*)d_out;

    // 1) fused QKV projection -> g_q/g_k/g_v in [B,H,T,Dh]
    dim3 g1(3072 / 128, BT / 128);
    gemm_nt_kernel<0><<<g1, 256>>>(x, Wq, bq, Wk, bk, Wv, bv, nullptr);

    // 2) RoPE in-place on q, k
    int rope_total = BH * TT * 32;
    rope_kernel<<<(rope_total + 255) / 256, 256>>>();

    // 3) flash attention -> g_attn in [B,T,D]
    dim3 g3(TT / 64, BH);
    attn_kernel<<<g3, 256>>>();

    // 4) output projection -> d_out
    dim3 g4(DM / 128, BT / 128);
    gemm_nt_kernel<1><<<g4, 256>>>(nullptr, Wo, bo, nullptr, nullptr,
                                   nullptr, nullptr, out);
}

// round 7
// speedup vs baseline: 1.3181x; 1.3181x over previous
#include <cuda_runtime.h>
#include <cuda_bf16.h>
#include <math.h>
#include <stdint.h>

// Problem constants
#define BB 2
#define TT 2048
#define DM 1024
#define NH 16
#define DH 64
#define BT (BB*TT)          // 4096
#define BH (BB*NH)          // 32

// Scratch (device globals; no allocation allowed)
__device__ float g_q[BH * TT * DH];     // [B,H,T,Dh]
__device__ float g_k[BH * TT * DH];
__device__ float g_v[BH * TT * DH];
__device__ float g_attn[BT * DM];       // [B,T,D]

// bf16 hi/lo split buffers
__device__ __nv_bfloat16 g_xhi[BT * DM];
__device__ __nv_bfloat16 g_xlo[BT * DM];
__device__ __nv_bfloat16 g_whi[4 * DM * DM];   // Wq,Wk,Wv,Wo
__device__ __nv_bfloat16 g_wlo[4 * DM * DM];
__device__ __nv_bfloat16 g_ahi[BT * DM];       // attn output split
__device__ __nv_bfloat16 g_alo[BT * DM];

// ---------------------------------------------------------------------------
// PTX helpers (plain sm_103 target: ldmatrix + mma.sync only, no 'a' features)
// ---------------------------------------------------------------------------
__device__ __forceinline__ uint32_t smem_u32(const void* p) {
    uint32_t a;
    asm("{ .reg .u64 t; cvta.to.shared.u64 t, %1; cvt.u32.u64 %0, t; }"
        : "=r"(a) : "l"(p));
    return a;
}

__device__ __forceinline__ void ldsm_x4(uint32_t* r, uint32_t addr) {
    asm volatile("ldmatrix.sync.aligned.m8n8.x4.shared.b16 {%0,%1,%2,%3}, [%4];"
                 : "=r"(r[0]), "=r"(r[1]), "=r"(r[2]), "=r"(r[3]) : "r"(addr));
}

__device__ __forceinline__ void mma_bf16(float* d, const uint32_t* a,
                                         uint32_t b0, uint32_t b1) {
    asm volatile(
        "mma.sync.aligned.m16n8k16.row.col.f32.bf16.bf16.f32 "
        "{%0,%1,%2,%3}, {%4,%5,%6,%7}, {%8,%9}, {%0,%1,%2,%3};"
        : "+f"(d[0]), "+f"(d[1]), "+f"(d[2]), "+f"(d[3])
        : "r"(a[0]), "r"(a[1]), "r"(a[2]), "r"(a[3]), "r"(b0), "r"(b1));
}

// ---------------------------------------------------------------------------
// fp32 -> bf16 hi/lo split kernels
// ---------------------------------------------------------------------------
__global__ __launch_bounds__(256)
void split_kernel(const float* __restrict__ src,
                  __nv_bfloat16* __restrict__ hi,
                  __nv_bfloat16* __restrict__ lo, int n)
{
    int i = blockIdx.x * blockDim.x + threadIdx.x;
    if (i >= n) return;
    float v = src[i];
    __nv_bfloat16 h = __float2bfloat16(v);
    float r = v - __bfloat162float(h);
    hi[i] = h;
    lo[i] = __float2bfloat16(r);
}

__global__ __launch_bounds__(256)
void split_w_kernel(const float* __restrict__ w0, const float* __restrict__ w1,
                    const float* __restrict__ w2, const float* __restrict__ w3)
{
    int i = blockIdx.x * blockDim.x + threadIdx.x;   // 0 .. 4M-1
    int w = i >> 20;
    int off = i & 0xFFFFF;
    const float* src = (w == 0) ? w0 : (w == 1) ? w1 : (w == 2) ? w2 : w3;
    float v = src[off];
    __nv_bfloat16 h = __float2bfloat16(v);
    float r = v - __bfloat162float(h);
    g_whi[i] = h;
    g_wlo[i] = __float2bfloat16(r);
}

// ---------------------------------------------------------------------------
// mma.sync split-bf16 GEMM: C[m,n] = sum_k A[m,k] W[n,k] + bias[n]
// CTA tile 128x128, K-chunk 32, 8 warps as 4(m) x 2(n); warp tile 32x64.
// Fragments via ldmatrix from padded smem (row stride 40 bf16 = 80B,
// conflict-free for ldmatrix row addressing).
// Split combos hi*hi + hi*lo + lo*hi accumulate in fp32 registers.
// MODE 0: A = x split, W/bias by n>>10 (Wq/Wk/Wv), out -> g_q/g_k/g_v [B,H,T,Dh]
// MODE 1: A = attn split, W = slot 3 (Wo), bias b0, out -> [M,1024]
// ---------------------------------------------------------------------------
#define PADK 40   // bf16 per smem row (32 data + 8 pad)

template <int MODE>
__global__ __launch_bounds__(256, 2)
void gemm_mma(const __nv_bfloat16* __restrict__ Ahi,
              const __nv_bfloat16* __restrict__ Alo,
              const float* __restrict__ b0, const float* __restrict__ b1,
              const float* __restrict__ b2, float* __restrict__ out)
{
    __shared__ __align__(16) __nv_bfloat16 sAh[128 * PADK];
    __shared__ __align__(16) __nv_bfloat16 sAl[128 * PADK];
    __shared__ __align__(16) __nv_bfloat16 sWh[128 * PADK];
    __shared__ __align__(16) __nv_bfloat16 sWl[128 * PADK];

    const int tid = threadIdx.x;
    const int lane = tid & 31, wid = tid >> 5;
    const int m0 = blockIdx.y * 128;
    const int n_base = blockIdx.x * 128;
    const int w = (MODE == 0) ? (n_base >> 10) : 3;
    const int n_loc0 = (MODE == 0) ? (n_base & 1023) : n_base;
    const int warp_m = wid >> 1;       // 0..3 -> 32-row slice
    const int warp_n = wid & 1;        // 0..1 -> 64-col slice

    // global load mapping: 2 threads per row, 16 bf16 each
    const int lrow = tid >> 1;
    const int lseg = (tid & 1) * 16;
    const __nv_bfloat16* pAh = Ahi + (size_t)(m0 + lrow) * DM + lseg;
    const __nv_bfloat16* pAl = Alo + (size_t)(m0 + lrow) * DM + lseg;
    const __nv_bfloat16* pWh = g_whi + ((size_t)w << 20) + (size_t)(n_loc0 + lrow) * DM + lseg;
    const __nv_bfloat16* pWl = g_wlo + ((size_t)w << 20) + (size_t)(n_loc0 + lrow) * DM + lseg;

    char* cAh = (char*)sAh; char* cAl = (char*)sAl;
    char* cWh = (char*)sWh; char* cWl = (char*)sWl;
    const uint32_t bAh = smem_u32(sAh), bAl = smem_u32(sAl);
    const uint32_t bWh = smem_u32(sWh), bWl = smem_u32(sWl);
    const uint32_t st_off = lrow * (PADK * 2) + lseg * 2;

    // ldmatrix per-lane tile offsets
    const int j = lane >> 3, r = lane & 7;
    const int mA = (j & 1) * 8 + r;       // A: t0=m0-7/k0, t1=m8-15/k0, t2=m0-7/k8, t3=m8-15/k8
    const int kA = (j >> 1) * 8;
    const int nB = (j >> 1) * 8 + r;      // B: t0=n0-7/k0, t1=n0-7/k8, t2=n8-15/k0, t3=n8-15/k8
    const int kB = (j & 1) * 8;

    float acc[2][8][4];
    #pragma unroll
    for (int i = 0; i < 2; i++)
        #pragma unroll
        for (int t = 0; t < 8; t++)
            #pragma unroll
            for (int e = 0; e < 4; e++) acc[i][t][e] = 0.0f;

    for (int c = 0; c < 32; c++) {
        if (c) __syncthreads();
        {
            const uint4* ga = (const uint4*)(pAh + c * 32);
            const uint4* gb = (const uint4*)(pAl + c * 32);
            const uint4* gc = (const uint4*)(pWh + c * 32);
            const uint4* gd = (const uint4*)(pWl + c * 32);
            *(uint4*)(cAh + st_off)      = ga[0];
            *(uint4*)(cAh + st_off + 16) = ga[1];
            *(uint4*)(cAl + st_off)      = gb[0];
            *(uint4*)(cAl + st_off + 16) = gb[1];
            *(uint4*)(cWh + st_off)      = gc[0];
            *(uint4*)(cWh + st_off + 16) = gc[1];
            *(uint4*)(cWl + st_off)      = gd[0];
            *(uint4*)(cWl + st_off + 16) = gd[1];
        }
        __syncthreads();

        #pragma unroll
        for (int kk = 0; kk < 2; kk++) {
            uint32_t ah[2][4], al[2][4];
            #pragma unroll
            for (int i = 0; i < 2; i++) {
                uint32_t roff = (uint32_t)(warp_m * 32 + i * 16 + mA) * (PADK * 2)
                              + (uint32_t)(kk * 16 + kA) * 2;
                ldsm_x4(ah[i], bAh + roff);
                ldsm_x4(al[i], bAl + roff);
            }
            #pragma unroll
            for (int p = 0; p < 4; p++) {
                uint32_t roff = (uint32_t)(warp_n * 64 + p * 16 + nB) * (PADK * 2)
                              + (uint32_t)(kk * 16 + kB) * 2;
                uint32_t wh[4], wl[4];
                ldsm_x4(wh, bWh + roff);
                ldsm_x4(wl, bWl + roff);
                #pragma unroll
                for (int i = 0; i < 2; i++) {
                    mma_bf16(acc[i][2*p],   ah[i], wh[0], wh[1]);
                    mma_bf16(acc[i][2*p+1], ah[i], wh[2], wh[3]);
                    mma_bf16(acc[i][2*p],   ah[i], wl[0], wl[1]);
                    mma_bf16(acc[i][2*p+1], ah[i], wl[2], wl[3]);
                    mma_bf16(acc[i][2*p],   al[i], wh[0], wh[1]);
                    mma_bf16(acc[i][2*p+1], al[i], wh[2], wh[3]);
                }
            }
        }
    }

    // Epilogue: C fragment c0,c1 -> (row gid, cols 2tig,2tig+1), c2,c3 -> row+8
    const float* bias = (MODE == 0) ? ((w == 0) ? b0 : (w == 1) ? b1 : b2) : b0;
    const int gid = lane >> 2, tig2 = (lane & 3) * 2;

    #pragma unroll
    for (int i = 0; i < 2; i++) {
        const int mr0 = m0 + warp_m * 32 + i * 16 + gid;
        #pragma unroll
        for (int t = 0; t < 8; t++) {
            const int nl = n_loc0 + warp_n * 64 + t * 8 + tig2;
            const float bx = bias[nl], by = bias[nl + 1];
            float2 v0 = make_float2(acc[i][t][0] + bx, acc[i][t][1] + by);
            float2 v1 = make_float2(acc[i][t][2] + bx, acc[i][t][3] + by);
            if (MODE == 0) {
                float* dst = (w == 0) ? g_q : (w == 1) ? g_k : g_v;
                const int h = nl >> 6, dh = nl & 63;
                {
                    const int b_ = mr0 >> 11, tt = mr0 & 2047;
                    *(float2*)&dst[(((size_t)(b_ * NH + h) * TT) + tt) * DH + dh] = v0;
                }
                {
                    const int m2 = mr0 + 8;
                    const int b_ = m2 >> 11, tt = m2 & 2047;
                    *(float2*)&dst[(((size_t)(b_ * NH + h) * TT) + tt) * DH + dh] = v1;
                }
            } else {
                *(float2*)&out[(size_t)mr0 * DM + nl]       = v0;
                *(float2*)&out[(size_t)(mr0 + 8) * DM + nl] = v1;
            }
        }
    }
}

// ---------------------------------------------------------------------------
// RoPE applied in-place to g_q and g_k (matches JAX fp32 rounding of angles).
// ---------------------------------------------------------------------------
__global__ __launch_bounds__(256)
void rope_kernel()
{
    int idx = blockIdx.x * blockDim.x + threadIdx.x;
    const int total = BH * TT * 32;
    if (idx >= total) return;
    int i  = idx & 31;
    int t  = (idx >> 5) & 2047;
    int bh = idx >> 16;

    double e   = -((double)(2 * i) / 64.0) * log(10000.0);
    float invf = (float)exp(e);
    float argf = (float)t * invf;
    double arg = (double)argf;
    float c = (float)cos(arg);
    float s = (float)sin(arg);

    size_t base = ((size_t)bh * TT + t) * DH;
    float q1 = g_q[base + i], q2 = g_q[base + i + 32];
    g_q[base + i]      = q1 * c - q2 * s;
    g_q[base + i + 32] = q2 * c + q1 * s;
    float k1 = g_k[base + i], k2 = g_k[base + i + 32];
    g_k[base + i]      = k1 * c - k2 * s;
    g_k[base + i + 32] = k2 * c + k1 * s;
}

// ---------------------------------------------------------------------------
// Flash attention (fp32): one block per (bh, 64-query tile), 256 threads.
// ---------------------------------------------------------------------------
__global__ __launch_bounds__(256)
void attn_kernel()
{
    __shared__ float Qt[64][64];
    __shared__ float KP[64][64];
    __shared__ float Vs[64][64];

    const int bh = blockIdx.y;
    const int q0 = blockIdx.x * 64;
    const int tid = threadIdx.x;
    const int tx = tid & 15;
    const int ty = tid >> 4;

    const float* qptr  = g_q + ((size_t)bh * TT + q0) * DH;
    const float* kbase = g_k + (size_t)bh * TT * DH;
    const float* vbase = g_v + (size_t)bh * TT * DH;

    {
        int row = tid >> 2, seg = tid & 3;
        #pragma unroll
        for (int rep = 0; rep < 4; rep++) {
            int c = (seg + rep * 4) * 4;
            float4 v = *(const float4*)(qptr + row * 64 + c);
            Qt[c + 0][row] = v.x * 0.125f;
            Qt[c + 1][row] = v.y * 0.125f;
            Qt[c + 2][row] = v.z * 0.125f;
            Qt[c + 3][row] = v.w * 0.125f;
        }
    }

    float m_r[4], l_r[4], o[4][4];
    #pragma unroll
    for (int i = 0; i < 4; i++) {
        m_r[i] = -INFINITY; l_r[i] = 0.0f;
        #pragma unroll
        for (int j = 0; j < 4; j++) o[i][j] = 0.0f;
    }

    for (int j0 = 0; j0 < TT; j0 += 64) {
        {
            int row = tid >> 2, seg = tid & 3;
            const float* krow = kbase + (size_t)(j0 + row) * 64;
            const float* vrow = vbase + (size_t)(j0 + row) * 64;
            #pragma unroll
            for (int rep = 0; rep < 4; rep++) {
                int c = (seg + rep * 4) * 4;
                float4 kv = *(const float4*)(krow + c);
                KP[c + 0][row] = kv.x;
                KP[c + 1][row] = kv.y;
                KP[c + 2][row] = kv.z;
                KP[c + 3][row] = kv.w;
                float4 vv = *(const float4*)(vrow + c);
                *(float4*)&Vs[row][c] = vv;
            }
        }
        __syncthreads();

        float s[4][4];
        #pragma unroll
        for (int i = 0; i < 4; i++)
            #pragma unroll
            for (int j = 0; j < 4; j++) s[i][j] = 0.0f;

        #pragma unroll 8
        for (int d = 0; d < 64; d++) {
            float4 qf = *(const float4*)&Qt[d][ty * 4];
            float4 kf = *(const float4*)&KP[d][tx * 4];
            float qa[4] = {qf.x, qf.y, qf.z, qf.w};
            float ka[4] = {kf.x, kf.y, kf.z, kf.w};
            #pragma unroll
            for (int i = 0; i < 4; i++)
                #pragma unroll
                for (int j = 0; j < 4; j++)
                    s[i][j] += qa[i] * ka[j];
        }

        #pragma unroll
        for (int i = 0; i < 4; i++) {
            float mx = fmaxf(fmaxf(s[i][0], s[i][1]), fmaxf(s[i][2], s[i][3]));
            #pragma unroll
            for (int off = 1; off < 16; off <<= 1)
                mx = fmaxf(mx, __shfl_xor_sync(0xffffffffu, mx, off));
            float mnew = fmaxf(m_r[i], mx);
            float corr = __expf(m_r[i] - mnew);
            float rs = 0.0f;
            #pragma unroll
            for (int j = 0; j < 4; j++) {
                s[i][j] = __expf(s[i][j] - mnew);
                rs += s[i][j];
            }
            #pragma unroll
            for (int off = 1; off < 16; off <<= 1)
                rs += __shfl_xor_sync(0xffffffffu, rs, off);
            l_r[i] = l_r[i] * corr + rs;
            m_r[i] = mnew;
            #pragma unroll
            for (int j = 0; j < 4; j++) o[i][j] *= corr;
        }

        __syncthreads();
        #pragma unroll
        for (int i = 0; i < 4; i++)
            *(float4*)&KP[ty * 4 + i][tx * 4] =
                make_float4(s[i][0], s[i][1], s[i][2], s[i][3]);
        __syncthreads();

        #pragma unroll 8
        for (int c = 0; c < 64; c++) {
            float4 vf = *(const float4*)&Vs[c][tx * 4];
            float va[4] = {vf.x, vf.y, vf.z, vf.w};
            float p0 = KP[ty*4+0][c];
            float p1 = KP[ty*4+1][c];
            float p2 = KP[ty*4+2][c];
            float p3 = KP[ty*4+3][c];
            #pragma unroll
            for (int j = 0; j < 4; j++) {
                o[0][j] += p0 * va[j];
                o[1][j] += p1 * va[j];
                o[2][j] += p2 * va[j];
                o[3][j] += p3 * va[j];
            }
        }
        __syncthreads();
    }

    const int b_ = bh >> 4, h = bh & 15;
    #pragma unroll
    for (int i = 0; i < 4; i++) {
        float inv = 1.0f / l_r[i];
        int t = q0 + ty * 4 + i;
        float4 r = make_float4(o[i][0]*inv, o[i][1]*inv, o[i][2]*inv, o[i][3]*inv);
        *(float4*)&g_attn[((size_t)(b_*TT + t)) * DM + h * DH + tx * 4] = r;
    }
}

// ---------------------------------------------------------------------------
extern "C" void kernel_launch(void* const* d_in, const int* in_sizes, int n_in,
                              void* d_out, int out_size)
{
    const float* x  = (const float*)d_in[0];
    const float* Wq = (const float*)d_in[1];
    const float* bq = (const float*)d_in[2];
    const float* Wk = (const float*)d_in[3];
    const float* bk = (const float*)d_in[4];
    const float* Wv = (const float*)d_in[5];
    const float* bv = (const float*)d_in[6];
    const float* Wo = (const float*)d_in[7];
    const float* bo = (const float*)d_in[8];
    float* out = (float*)d_out;

    __nv_bfloat16 *xhi, *xlo, *ahi, *alo;
    cudaGetSymbolAddress((void**)&xhi, g_xhi);
    cudaGetSymbolAddress((void**)&xlo, g_xlo);
    cudaGetSymbolAddress((void**)&ahi, g_ahi);
    cudaGetSymbolAddress((void**)&alo, g_alo);
    float* attn_ptr;
    cudaGetSymbolAddress((void**)&attn_ptr, g_attn);

    // 0) split x and weights into bf16 hi/lo
    split_kernel<<<(BT * DM + 255) / 256, 256>>>(x, xhi, xlo, BT * DM);
    split_w_kernel<<<(4 * DM * DM + 255) / 256, 256>>>(Wq, Wk, Wv, Wo);

    // 1) QKV projection (mma.sync) -> g_q/g_k/g_v in [B,H,T,Dh]
    dim3 g1(3072 / 128, BT / 128);
    gemm_mma<0><<<g1, 256>>>(xhi, xlo, bq, bk, bv, nullptr);

    // 2) RoPE in-place on q, k
    rope_kernel<<<(BH * TT * 32 + 255) / 256, 256>>>();

    // 3) flash attention -> g_attn in [B,T,D]
    dim3 g3(TT / 64, BH);
    attn_kernel<<<g3, 256>>>();

    // 4) split attn output, then output projection (mma.sync) -> d_out
    split_kernel<<<(BT * DM + 255) / 256, 256>>>(attn_ptr, ahi, alo, BT * DM);
    dim3 g4(DM / 128, BT / 128);
    gemm_mma<1><<<g4, 256>>>(ahi, alo, bo, nullptr, nullptr, out);
}

// round 8
// speedup vs baseline: 2.5933x; 1.9674x over previous
#include <cuda_runtime.h>
#include <cuda_bf16.h>
#include <math.h>
#include <stdint.h>

// Problem constants
#define BB 2
#define TT 2048
#define DM 1024
#define NH 16
#define DH 64
#define BT (BB*TT)          // 4096
#define BH (BB*NH)          // 32

// Scratch (device globals; no allocation allowed)
__device__ float g_q[BH * TT * DH];     // [B,H,T,Dh] fp32 (pre-rope)
__device__ float g_k[BH * TT * DH];

// bf16 hi/lo split buffers
__device__ __nv_bfloat16 g_xhi[BT * DM];
__device__ __nv_bfloat16 g_xlo[BT * DM];
__device__ __nv_bfloat16 g_whi[4 * DM * DM];   // Wq,Wk,Wv,Wo
__device__ __nv_bfloat16 g_wlo[4 * DM * DM];
__device__ __nv_bfloat16 g_qhi[BH * TT * DH];  // roped, scaled by 0.125
__device__ __nv_bfloat16 g_qlo[BH * TT * DH];
__device__ __nv_bfloat16 g_khi[BH * TT * DH];  // roped
__device__ __nv_bfloat16 g_klo[BH * TT * DH];
__device__ __nv_bfloat16 g_vhi[BH * TT * DH];
__device__ __nv_bfloat16 g_vlo[BH * TT * DH];
__device__ __nv_bfloat16 g_ahi[BT * DM];       // attn output split [B,T,D]
__device__ __nv_bfloat16 g_alo[BT * DM];

// ---------------------------------------------------------------------------
// PTX helpers (plain sm_103 target: ldmatrix + mma.sync only)
// ---------------------------------------------------------------------------
__device__ __forceinline__ uint32_t smem_u32(const void* p) {
    uint32_t a;
    asm("{ .reg .u64 t; cvta.to.shared.u64 t, %1; cvt.u32.u64 %0, t; }"
        : "=r"(a) : "l"(p));
    return a;
}

__device__ __forceinline__ void ldsm_x4(uint32_t* r, uint32_t addr) {
    asm volatile("ldmatrix.sync.aligned.m8n8.x4.shared.b16 {%0,%1,%2,%3}, [%4];"
                 : "=r"(r[0]), "=r"(r[1]), "=r"(r[2]), "=r"(r[3]) : "r"(addr));
}

__device__ __forceinline__ void ldsm_x4_t(uint32_t* r, uint32_t addr) {
    asm volatile("ldmatrix.sync.aligned.m8n8.x4.trans.shared.b16 {%0,%1,%2,%3}, [%4];"
                 : "=r"(r[0]), "=r"(r[1]), "=r"(r[2]), "=r"(r[3]) : "r"(addr));
}

__device__ __forceinline__ void mma_bf16(float* d, const uint32_t* a,
                                         uint32_t b0, uint32_t b1) {
    asm volatile(
        "mma.sync.aligned.m16n8k16.row.col.f32.bf16.bf16.f32 "
        "{%0,%1,%2,%3}, {%4,%5,%6,%7}, {%8,%9}, {%0,%1,%2,%3};"
        : "+f"(d[0]), "+f"(d[1]), "+f"(d[2]), "+f"(d[3])
        : "r"(a[0]), "r"(a[1]), "r"(a[2]), "r"(a[3]), "r"(b0), "r"(b1));
}

__device__ __forceinline__ uint32_t pack_bf16x2(float x, float y) {
    __nv_bfloat162 h = __floats2bfloat162_rn(x, y);
    return *(uint32_t*)&h;
}

// split a float pair into bf16 hi pair + bf16 lo (residual) pair
__device__ __forceinline__ void split2(float x, float y,
                                       uint32_t& hv, uint32_t& lv) {
    __nv_bfloat16 h0 = __float2bfloat16(x);
    __nv_bfloat16 h1 = __float2bfloat16(y);
    hv = ((uint32_t)*(uint16_t*)&h1 << 16) | *(uint16_t*)&h0;
    lv = pack_bf16x2(x - __bfloat162float(h0), y - __bfloat162float(h1));
}

// ---------------------------------------------------------------------------
// fp32 -> bf16 hi/lo split kernels
// ---------------------------------------------------------------------------
__global__ __launch_bounds__(256)
void split_kernel(const float* __restrict__ src,
                  __nv_bfloat16* __restrict__ hi,
                  __nv_bfloat16* __restrict__ lo, int n)
{
    int i = blockIdx.x * blockDim.x + threadIdx.x;
    if (i >= n) return;
    float v = src[i];
    __nv_bfloat16 h = __float2bfloat16(v);
    float r = v - __bfloat162float(h);
    hi[i] = h;
    lo[i] = __float2bfloat16(r);
}

__global__ __launch_bounds__(256)
void split_w_kernel(const float* __restrict__ w0, const float* __restrict__ w1,
                    const float* __restrict__ w2, const float* __restrict__ w3)
{
    int i = blockIdx.x * blockDim.x + threadIdx.x;   // 0 .. 4M-1
    int w = i >> 20;
    int off = i & 0xFFFFF;
    const float* src = (w == 0) ? w0 : (w == 1) ? w1 : (w == 2) ? w2 : w3;
    float v = src[off];
    __nv_bfloat16 h = __float2bfloat16(v);
    float r = v - __bfloat162float(h);
    g_whi[i] = h;
    g_wlo[i] = __float2bfloat16(r);
}

// ---------------------------------------------------------------------------
// mma.sync split-bf16 GEMM (verified in R7).
// MODE 0: A = x split, W/bias by n>>10 (Wq/Wk/Wv).
//         w<2 -> fp32 g_q/g_k [B,H,T,Dh];  w==2 -> bf16 split g_vhi/g_vlo
// MODE 1: A = attn split, W = slot 3 (Wo), bias b0, out -> [M,1024] fp32
// ---------------------------------------------------------------------------
#define PADK 40   // bf16 per smem row (32 data + 8 pad)

template <int MODE>
__global__ __launch_bounds__(256, 2)
void gemm_mma(const __nv_bfloat16* __restrict__ Ahi,
              const __nv_bfloat16* __restrict__ Alo,
              const float* __restrict__ b0, const float* __restrict__ b1,
              const float* __restrict__ b2, float* __restrict__ out)
{
    __shared__ __align__(16) __nv_bfloat16 sAh[128 * PADK];
    __shared__ __align__(16) __nv_bfloat16 sAl[128 * PADK];
    __shared__ __align__(16) __nv_bfloat16 sWh[128 * PADK];
    __shared__ __align__(16) __nv_bfloat16 sWl[128 * PADK];

    const int tid = threadIdx.x;
    const int lane = tid & 31, wid = tid >> 5;
    const int m0 = blockIdx.y * 128;
    const int n_base = blockIdx.x * 128;
    const int w = (MODE == 0) ? (n_base >> 10) : 3;
    const int n_loc0 = (MODE == 0) ? (n_base & 1023) : n_base;
    const int warp_m = wid >> 1;
    const int warp_n = wid & 1;

    const int lrow = tid >> 1;
    const int lseg = (tid & 1) * 16;
    const __nv_bfloat16* pAh = Ahi + (size_t)(m0 + lrow) * DM + lseg;
    const __nv_bfloat16* pAl = Alo + (size_t)(m0 + lrow) * DM + lseg;
    const __nv_bfloat16* pWh = g_whi + ((size_t)w << 20) + (size_t)(n_loc0 + lrow) * DM + lseg;
    const __nv_bfloat16* pWl = g_wlo + ((size_t)w << 20) + (size_t)(n_loc0 + lrow) * DM + lseg;

    char* cAh = (char*)sAh; char* cAl = (char*)sAl;
    char* cWh = (char*)sWh; char* cWl = (char*)sWl;
    const uint32_t bAh = smem_u32(sAh), bAl = smem_u32(sAl);
    const uint32_t bWh = smem_u32(sWh), bWl = smem_u32(sWl);
    const uint32_t st_off = lrow * (PADK * 2) + lseg * 2;

    const int j = lane >> 3, r = lane & 7;
    const int mA = (j & 1) * 8 + r;
    const int kA = (j >> 1) * 8;
    const int nB = (j >> 1) * 8 + r;
    const int kB = (j & 1) * 8;

    float acc[2][8][4];
    #pragma unroll
    for (int i = 0; i < 2; i++)
        #pragma unroll
        for (int t = 0; t < 8; t++)
            #pragma unroll
            for (int e = 0; e < 4; e++) acc[i][t][e] = 0.0f;

    for (int c = 0; c < 32; c++) {
        if (c) __syncthreads();
        {
            const uint4* ga = (const uint4*)(pAh + c * 32);
            const uint4* gb = (const uint4*)(pAl + c * 32);
            const uint4* gc = (const uint4*)(pWh + c * 32);
            const uint4* gd = (const uint4*)(pWl + c * 32);
            *(uint4*)(cAh + st_off)      = ga[0];
            *(uint4*)(cAh + st_off + 16) = ga[1];
            *(uint4*)(cAl + st_off)      = gb[0];
            *(uint4*)(cAl + st_off + 16) = gb[1];
            *(uint4*)(cWh + st_off)      = gc[0];
            *(uint4*)(cWh + st_off + 16) = gc[1];
            *(uint4*)(cWl + st_off)      = gd[0];
            *(uint4*)(cWl + st_off + 16) = gd[1];
        }
        __syncthreads();

        #pragma unroll
        for (int kk = 0; kk < 2; kk++) {
            uint32_t ah[2][4], al[2][4];
            #pragma unroll
            for (int i = 0; i < 2; i++) {
                uint32_t roff = (uint32_t)(warp_m * 32 + i * 16 + mA) * (PADK * 2)
                              + (uint32_t)(kk * 16 + kA) * 2;
                ldsm_x4(ah[i], bAh + roff);
                ldsm_x4(al[i], bAl + roff);
            }
            #pragma unroll
            for (int p = 0; p < 4; p++) {
                uint32_t roff = (uint32_t)(warp_n * 64 + p * 16 + nB) * (PADK * 2)
                              + (uint32_t)(kk * 16 + kB) * 2;
                uint32_t wh[4], wl[4];
                ldsm_x4(wh, bWh + roff);
                ldsm_x4(wl, bWl + roff);
                #pragma unroll
                for (int i = 0; i < 2; i++) {
                    mma_bf16(acc[i][2*p],   ah[i], wh[0], wh[1]);
                    mma_bf16(acc[i][2*p+1], ah[i], wh[2], wh[3]);
                    mma_bf16(acc[i][2*p],   ah[i], wl[0], wl[1]);
                    mma_bf16(acc[i][2*p+1], ah[i], wl[2], wl[3]);
                    mma_bf16(acc[i][2*p],   al[i], wh[0], wh[1]);
                    mma_bf16(acc[i][2*p+1], al[i], wh[2], wh[3]);
                }
            }
        }
    }

    const float* bias = (MODE == 0) ? ((w == 0) ? b0 : (w == 1) ? b1 : b2) : b0;
    const int gid = lane >> 2, tig2 = (lane & 3) * 2;

    #pragma unroll
    for (int i = 0; i < 2; i++) {
        const int mr0 = m0 + warp_m * 32 + i * 16 + gid;
        #pragma unroll
        for (int t = 0; t < 8; t++) {
            const int nl = n_loc0 + warp_n * 64 + t * 8 + tig2;
            const float bx = bias[nl], by = bias[nl + 1];
            float2 v0 = make_float2(acc[i][t][0] + bx, acc[i][t][1] + by);
            float2 v1 = make_float2(acc[i][t][2] + bx, acc[i][t][3] + by);
            if (MODE == 0) {
                const int h = nl >> 6, dh = nl & 63;
                if (w == 2) {
                    // V: write bf16 hi/lo split directly
                    #pragma unroll
                    for (int hv = 0; hv < 2; hv++) {
                        const int m_ = mr0 + hv * 8;
                        const int b_ = m_ >> 11, tt = m_ & 2047;
                        size_t e = (((size_t)(b_ * NH + h) * TT) + tt) * DH + dh;
                        float vx = hv ? v1.x : v0.x, vy = hv ? v1.y : v0.y;
                        uint32_t hb, lb;
                        split2(vx, vy, hb, lb);
                        *(uint32_t*)&g_vhi[e] = hb;
                        *(uint32_t*)&g_vlo[e] = lb;
                    }
                } else {
                    float* dst = (w == 0) ? g_q : g_k;
                    {
                        const int b_ = mr0 >> 11, tt = mr0 & 2047;
                        *(float2*)&dst[(((size_t)(b_ * NH + h) * TT) + tt) * DH + dh] = v0;
                    }
                    {
                        const int m2 = mr0 + 8;
                        const int b_ = m2 >> 11, tt = m2 & 2047;
                        *(float2*)&dst[(((size_t)(b_ * NH + h) * TT) + tt) * DH + dh] = v1;
                    }
                }
            } else {
                *(float2*)&out[(size_t)mr0 * DM + nl]       = v0;
                *(float2*)&out[(size_t)(mr0 + 8) * DM + nl] = v1;
            }
        }
    }
}

// ---------------------------------------------------------------------------
// RoPE + bf16 hi/lo split.  One thread per (t, i) pair; trig computed once,
// applied across all 32 (b,h) planes.  Q additionally scaled by 1/sqrt(64).
// Matches JAX fp32 rounding: arg = fp32(t)*fp32(inv_freq); trig in double.
// ---------------------------------------------------------------------------
__global__ __launch_bounds__(256)
void rope_split_kernel()
{
    int idx = blockIdx.x * blockDim.x + threadIdx.x;
    if (idx >= TT * 32) return;
    int i = idx & 31;
    int t = idx >> 5;

    double e   = -((double)(2 * i) / 64.0) * log(10000.0);
    float invf = (float)exp(e);
    float argf = (float)t * invf;
    double arg = (double)argf;
    float c = (float)cos(arg);
    float s = (float)sin(arg);

    #pragma unroll 4
    for (int bh = 0; bh < BH; bh++) {
        size_t base = ((size_t)bh * TT + t) * DH;
        float q1 = g_q[base + i], q2 = g_q[base + i + 32];
        float rq1 = (q1 * c - q2 * s) * 0.125f;
        float rq2 = (q2 * c + q1 * s) * 0.125f;
        __nv_bfloat16 h;
        h = __float2bfloat16(rq1); g_qhi[base + i]      = h;
        g_qlo[base + i]      = __float2bfloat16(rq1 - __bfloat162float(h));
        h = __float2bfloat16(rq2); g_qhi[base + i + 32] = h;
        g_qlo[base + i + 32] = __float2bfloat16(rq2 - __bfloat162float(h));

        float k1 = g_k[base + i], k2 = g_k[base + i + 32];
        float rk1 = k1 * c - k2 * s;
        float rk2 = k2 * c + k1 * s;
        h = __float2bfloat16(rk1); g_khi[base + i]      = h;
        g_klo[base + i]      = __float2bfloat16(rk1 - __bfloat162float(h));
        h = __float2bfloat16(rk2); g_khi[base + i + 32] = h;
        g_klo[base + i + 32] = __float2bfloat16(rk2 - __bfloat162float(h));
    }
}

// ---------------------------------------------------------------------------
// Flash attention on mma.sync (bf16 hi/lo split everywhere, fp32 accum).
// Block: 128 threads (4 warps), 64 q-rows; warp owns 16 q-rows.
// S = QK^T: Q,K split (3 combos).  PV: P split in regs (C-frag == A-frag
// layout), V split via ldmatrix.trans (3 combos).  Online softmax with
// quad-lane shfl reductions.  Output -> g_ahi/g_alo [B,T,D].
// ---------------------------------------------------------------------------
#define ASTR 72   // bf16 per smem row (64 data + 8 pad); 144B stride

__global__ __launch_bounds__(128)
void attn_mma_kernel()
{
    __shared__ __align__(16) __nv_bfloat16 sKh[64 * ASTR];
    __shared__ __align__(16) __nv_bfloat16 sKl[64 * ASTR];
    __shared__ __align__(16) __nv_bfloat16 sVh[64 * ASTR];
    __shared__ __align__(16) __nv_bfloat16 sVl[64 * ASTR];

    const int bh = blockIdx.y;
    const int q0 = blockIdx.x * 64;
    const int tid = threadIdx.x;
    const int lane = tid & 31, wid = tid >> 5;
    const int j = lane >> 3, r = lane & 7;

    const size_t headoff = (size_t)bh * TT * DH;
    const __nv_bfloat16* pQh = g_qhi + headoff + (size_t)q0 * DH;
    const __nv_bfloat16* pQl = g_qlo + headoff + (size_t)q0 * DH;
    const __nv_bfloat16* pKh = g_khi + headoff;
    const __nv_bfloat16* pKl = g_klo + headoff;
    const __nv_bfloat16* pVh = g_vhi + headoff;
    const __nv_bfloat16* pVl = g_vlo + headoff;

    const uint32_t bKh = smem_u32(sKh), bKl = smem_u32(sKl);
    const uint32_t bVh = smem_u32(sVh), bVl = smem_u32(sVl);

    // tile-load mapping: 2 threads per row, 32 bf16 (4 uint4) each
    const int lrow = tid >> 1, lhalf = (tid & 1) * 32;
    const uint32_t sm_off = lrow * (ASTR * 2) + lhalf * 2;

    // ---- load Q tile into K buffers, extract fragments ----
    {
        const uint4* gh = (const uint4*)(pQh + (size_t)lrow * DH + lhalf);
        const uint4* gl = (const uint4*)(pQl + (size_t)lrow * DH + lhalf);
        #pragma unroll
        for (int s2 = 0; s2 < 4; s2++) {
            *(uint4*)((char*)sKh + sm_off + s2 * 16) = gh[s2];
            *(uint4*)((char*)sKl + sm_off + s2 * 16) = gl[s2];
        }
    }
    __syncthreads();

    uint32_t qh[4][4], ql[4][4];
    {
        const int mA = (j & 1) * 8 + r, kA = (j >> 1) * 8;
        #pragma unroll
        for (int kk = 0; kk < 4; kk++) {
            uint32_t off = (uint32_t)(wid * 16 + mA) * (ASTR * 2)
                         + (uint32_t)(kk * 16 + kA) * 2;
            ldsm_x4(qh[kk], bKh + off);
            ldsm_x4(ql[kk], bKl + off);
        }
    }

    const int nB = (j >> 1) * 8 + r, kB = (j & 1) * 8;   // K ldsm lanes
    const int vk = lane & 15, vn8 = (lane >> 4) * 8;     // V trans lanes

    float m_r[2] = {-INFINITY, -INFINITY};
    float l_r[2] = {0.0f, 0.0f};
    float oacc[8][4];
    #pragma unroll
    for (int t = 0; t < 8; t++)
        #pragma unroll
        for (int e = 0; e < 4; e++) oacc[t][e] = 0.0f;

    for (int j0 = 0; j0 < TT; j0 += 64) {
        __syncthreads();   // prior iteration's reads of K/V done (and Q extract)
        {
            const uint4* a = (const uint4*)(pKh + (size_t)(j0 + lrow) * DH + lhalf);
            const uint4* b = (const uint4*)(pKl + (size_t)(j0 + lrow) * DH + lhalf);
            const uint4* c = (const uint4*)(pVh + (size_t)(j0 + lrow) * DH + lhalf);
            const uint4* d = (const uint4*)(pVl + (size_t)(j0 + lrow) * DH + lhalf);
            #pragma unroll
            for (int s2 = 0; s2 < 4; s2++) {
                *(uint4*)((char*)sKh + sm_off + s2 * 16) = a[s2];
                *(uint4*)((char*)sKl + sm_off + s2 * 16) = b[s2];
                *(uint4*)((char*)sVh + sm_off + s2 * 16) = c[s2];
                *(uint4*)((char*)sVl + sm_off + s2 * 16) = d[s2];
            }
        }
        __syncthreads();

        // ---- S = Q K^T (3 split combos) ----
        float sacc[8][4];
        #pragma unroll
        for (int t = 0; t < 8; t++)
            #pragma unroll
            for (int e = 0; e < 4; e++) sacc[t][e] = 0.0f;

        #pragma unroll
        for (int kk = 0; kk < 4; kk++) {
            #pragma unroll
            for (int p = 0; p < 4; p++) {
                uint32_t off = (uint32_t)(p * 16 + nB) * (ASTR * 2)
                             + (uint32_t)(kk * 16 + kB) * 2;
                uint32_t kh4[4], kl4[4];
                ldsm_x4(kh4, bKh + off);
                ldsm_x4(kl4, bKl + off);
                mma_bf16(sacc[2*p],   qh[kk], kh4[0], kh4[1]);
                mma_bf16(sacc[2*p+1], qh[kk], kh4[2], kh4[3]);
                mma_bf16(sacc[2*p],   qh[kk], kl4[0], kl4[1]);
                mma_bf16(sacc[2*p+1], qh[kk], kl4[2], kl4[3]);
                mma_bf16(sacc[2*p],   ql[kk], kh4[0], kh4[1]);
                mma_bf16(sacc[2*p+1], ql[kk], kh4[2], kh4[3]);
            }
        }

        // ---- online softmax (rows gid and gid+8; quad lanes share a row) ----
        float mx0 = -INFINITY, mx1 = -INFINITY;
        #pragma unroll
        for (int t = 0; t < 8; t++) {
            mx0 = fmaxf(mx0, fmaxf(sacc[t][0], sacc[t][1]));
            mx1 = fmaxf(mx1, fmaxf(sacc[t][2], sacc[t][3]));
        }
        #pragma unroll
        for (int off = 1; off < 4; off <<= 1) {
            mx0 = fmaxf(mx0, __shfl_xor_sync(0xffffffffu, mx0, off));
            mx1 = fmaxf(mx1, __shfl_xor_sync(0xffffffffu, mx1, off));
        }
        float mn0 = fmaxf(m_r[0], mx0), mn1 = fmaxf(m_r[1], mx1);
        float cr0 = __expf(m_r[0] - mn0), cr1 = __expf(m_r[1] - mn1);
        float rs0 = 0.0f, rs1 = 0.0f;
        #pragma unroll
        for (int t = 0; t < 8; t++) {
            sacc[t][0] = __expf(sacc[t][0] - mn0);
            sacc[t][1] = __expf(sacc[t][1] - mn0);
            sacc[t][2] = __expf(sacc[t][2] - mn1);
            sacc[t][3] = __expf(sacc[t][3] - mn1);
            rs0 += sacc[t][0] + sacc[t][1];
            rs1 += sacc[t][2] + sacc[t][3];
        }
        #pragma unroll
        for (int off = 1; off < 4; off <<= 1) {
            rs0 += __shfl_xor_sync(0xffffffffu, rs0, off);
            rs1 += __shfl_xor_sync(0xffffffffu, rs1, off);
        }
        l_r[0] = l_r[0] * cr0 + rs0;  m_r[0] = mn0;
        l_r[1] = l_r[1] * cr1 + rs1;  m_r[1] = mn1;
        #pragma unroll
        for (int t = 0; t < 8; t++) {
            oacc[t][0] *= cr0;  oacc[t][1] *= cr0;
            oacc[t][2] *= cr1;  oacc[t][3] *= cr1;
        }

        // ---- O += P V (P split in regs, V split via ldmatrix.trans) ----
        #pragma unroll
        for (int kc = 0; kc < 4; kc++) {
            uint32_t phi[4], plo[4];
            split2(sacc[2*kc][0],   sacc[2*kc][1],   phi[0], plo[0]);
            split2(sacc[2*kc][2],   sacc[2*kc][3],   phi[1], plo[1]);
            split2(sacc[2*kc+1][0], sacc[2*kc+1][1], phi[2], plo[2]);
            split2(sacc[2*kc+1][2], sacc[2*kc+1][3], phi[3], plo[3]);
            #pragma unroll
            for (int p = 0; p < 4; p++) {
                uint32_t off = (uint32_t)(kc * 16 + vk) * (ASTR * 2)
                             + (uint32_t)(p * 16 + vn8) * 2;
                uint32_t vh4[4], vl4[4];
                ldsm_x4_t(vh4, bVh + off);
                ldsm_x4_t(vl4, bVl + off);
                mma_bf16(oacc[2*p],   phi, vh4[0], vh4[1]);
                mma_bf16(oacc[2*p+1], phi, vh4[2], vh4[3]);
                mma_bf16(oacc[2*p],   phi, vl4[0], vl4[1]);
                mma_bf16(oacc[2*p+1], phi, vl4[2], vl4[3]);
                mma_bf16(oacc[2*p],   plo, vh4[0], vh4[1]);
                mma_bf16(oacc[2*p+1], plo, vh4[2], vh4[3]);
            }
        }
    }

    // ---- epilogue: normalize, split to bf16 hi/lo, write [B,T,D] ----
    const int gid = lane >> 2, tg2 = (lane & 3) * 2;
    const float inv0 = 1.0f / l_r[0], inv1 = 1.0f / l_r[1];
    const int b_ = bh >> 4, h = bh & 15;
    const int row0 = q0 + wid * 16 + gid;
    uint32_t* ahi32 = (uint32_t*)g_ahi;
    uint32_t* alo32 = (uint32_t*)g_alo;

    #pragma unroll
    for (int t = 0; t < 8; t++) {
        const int col = h * 64 + t * 8 + tg2;
        uint32_t hv, lv;
        split2(oacc[t][0] * inv0, oacc[t][1] * inv0, hv, lv);
        size_t e0 = (((size_t)(b_ * TT + row0)) * DM + col) >> 1;
        ahi32[e0] = hv;  alo32[e0] = lv;
        split2(oacc[t][2] * inv1, oacc[t][3] * inv1, hv, lv);
        size_t e1 = (((size_t)(b_ * TT + row0 + 8)) * DM + col) >> 1;
        ahi32[e1] = hv;  alo32[e1] = lv;
    }
}

// ---------------------------------------------------------------------------
extern "C" void kernel_launch(void* const* d_in, const int* in_sizes, int n_in,
                              void* d_out, int out_size)
{
    const float* x  = (const float*)d_in[0];
    const float* Wq = (const float*)d_in[1];
    const float* bq = (const float*)d_in[2];
    const float* Wk = (const float*)d_in[3];
    const float* bk = (const float*)d_in[4];
    const float* Wv = (const float*)d_in[5];
    const float* bv = (const float*)d_in[6];
    const float* Wo = (const float*)d_in[7];
    const float* bo = (const float*)d_in[8];
    float* out = (float*)d_out;

    __nv_bfloat16 *xhi, *xlo, *ahi, *alo;
    cudaGetSymbolAddress((void**)&xhi, g_xhi);
    cudaGetSymbolAddress((void**)&xlo, g_xlo);
    cudaGetSymbolAddress((void**)&ahi, g_ahi);
    cudaGetSymbolAddress((void**)&alo, g_alo);

    // 0) split x and weights into bf16 hi/lo
    split_kernel<<<(BT * DM + 255) / 256, 256>>>(x, xhi, xlo, BT * DM);
    split_w_kernel<<<(4 * DM * DM + 255) / 256, 256>>>(Wq, Wk, Wv, Wo);

    // 1) QKV projection: q,k -> fp32 [B,H,T,Dh]; v -> bf16 split
    dim3 g1(3072 / 128, BT / 128);
    gemm_mma<0><<<g1, 256>>>(xhi, xlo, bq, bk, bv, nullptr);

    // 2) RoPE + scale + bf16 split for q,k
    rope_split_kernel<<<(TT * 32 + 255) / 256, 256>>>();

    // 3) flash attention (mma.sync) -> g_ahi/g_alo [B,T,D]
    dim3 g3(TT / 64, BH);
    attn_mma_kernel<<<g3, 128>>>();

    // 4) output projection -> d_out
    dim3 g4(DM / 128, BT / 128);
    gemm_mma<1><<<g4, 256>>>(ahi, alo, bo, nullptr, nullptr, out);
}

// round 9
// speedup vs baseline: 2.7886x; 1.0753x over previous
#include <cuda_runtime.h>
#include <cuda_bf16.h>
#include <math.h>
#include <stdint.h>

// Problem constants
#define BB 2
#define TT 2048
#define DM 1024
#define NH 16
#define DH 64
#define BT (BB*TT)          // 4096
#define BH (BB*NH)          // 32

// Scratch (device globals; no allocation allowed)
__device__ float g_q[BH * TT * DH];     // [B,H,T,Dh] fp32 (pre-rope)
__device__ float g_k[BH * TT * DH];
__device__ float g_cosv[TT * 32];
__device__ float g_sinv[TT * 32];

// bf16 hi/lo split buffers
__device__ __nv_bfloat16 g_xhi[BT * DM];
__device__ __nv_bfloat16 g_xlo[BT * DM];
__device__ __nv_bfloat16 g_whi[4 * DM * DM];   // Wq,Wk,Wv,Wo
__device__ __nv_bfloat16 g_wlo[4 * DM * DM];
__device__ __nv_bfloat16 g_qhi[BH * TT * DH];  // roped, scaled by 0.125
__device__ __nv_bfloat16 g_qlo[BH * TT * DH];
__device__ __nv_bfloat16 g_khi[BH * TT * DH];  // roped
__device__ __nv_bfloat16 g_klo[BH * TT * DH];
__device__ __nv_bfloat16 g_vhi[BH * TT * DH];
__device__ __nv_bfloat16 g_vlo[BH * TT * DH];
__device__ __nv_bfloat16 g_ahi[BT * DM];       // attn output split [B,T,D]
__device__ __nv_bfloat16 g_alo[BT * DM];

// ---------------------------------------------------------------------------
// PTX helpers (plain sm_103 target: ldmatrix + mma.sync + cp.async)
// ---------------------------------------------------------------------------
__device__ __forceinline__ uint32_t smem_u32(const void* p) {
    uint32_t a;
    asm("{ .reg .u64 t; cvta.to.shared.u64 t, %1; cvt.u32.u64 %0, t; }"
        : "=r"(a) : "l"(p));
    return a;
}

__device__ __forceinline__ void ldsm_x4(uint32_t* r, uint32_t addr) {
    asm volatile("ldmatrix.sync.aligned.m8n8.x4.shared.b16 {%0,%1,%2,%3}, [%4];"
                 : "=r"(r[0]), "=r"(r[1]), "=r"(r[2]), "=r"(r[3]) : "r"(addr));
}

__device__ __forceinline__ void ldsm_x4_t(uint32_t* r, uint32_t addr) {
    asm volatile("ldmatrix.sync.aligned.m8n8.x4.trans.shared.b16 {%0,%1,%2,%3}, [%4];"
                 : "=r"(r[0]), "=r"(r[1]), "=r"(r[2]), "=r"(r[3]) : "r"(addr));
}

__device__ __forceinline__ void mma_bf16(float* d, const uint32_t* a,
                                         uint32_t b0, uint32_t b1) {
    asm volatile(
        "mma.sync.aligned.m16n8k16.row.col.f32.bf16.bf16.f32 "
        "{%0,%1,%2,%3}, {%4,%5,%6,%7}, {%8,%9}, {%0,%1,%2,%3};"
        : "+f"(d[0]), "+f"(d[1]), "+f"(d[2]), "+f"(d[3])
        : "r"(a[0]), "r"(a[1]), "r"(a[2]), "r"(a[3]), "r"(b0), "r"(b1));
}

__device__ __forceinline__ void cp16(uint32_t s, const void* g) {
    asm volatile("cp.async.cg.shared.global [%0], [%1], 16;" :: "r"(s), "l"(g));
}
__device__ __forceinline__ void cp_commit() {
    asm volatile("cp.async.commit_group;" ::: "memory");
}
__device__ __forceinline__ void cp_wait1() {
    asm volatile("cp.async.wait_group 1;" ::: "memory");
}
__device__ __forceinline__ void cp_wait0() {
    asm volatile("cp.async.wait_group 0;" ::: "memory");
}

__device__ __forceinline__ uint32_t pack_bf16x2(float x, float y) {
    __nv_bfloat162 h = __floats2bfloat162_rn(x, y);
    return *(uint32_t*)&h;
}

// split a float pair into bf16 hi pair + bf16 lo (residual) pair
__device__ __forceinline__ void split2(float x, float y,
                                       uint32_t& hv, uint32_t& lv) {
    __nv_bfloat16 h0 = __float2bfloat16(x);
    __nv_bfloat16 h1 = __float2bfloat16(y);
    hv = ((uint32_t)*(uint16_t*)&h1 << 16) | *(uint16_t*)&h0;
    lv = pack_bf16x2(x - __bfloat162float(h0), y - __bfloat162float(h1));
}

// ---------------------------------------------------------------------------
// fp32 -> bf16 hi/lo split kernels (vectorized: 2 elements / thread)
// ---------------------------------------------------------------------------
__global__ __launch_bounds__(256)
void split2_kernel(const float* __restrict__ src,
                   __nv_bfloat16* __restrict__ hi,
                   __nv_bfloat16* __restrict__ lo, int n2)
{
    int idx = blockIdx.x * blockDim.x + threadIdx.x;
    if (idx >= n2) return;
    float2 v = ((const float2*)src)[idx];
    uint32_t hv, lv;
    split2(v.x, v.y, hv, lv);
    ((uint32_t*)hi)[idx] = hv;
    ((uint32_t*)lo)[idx] = lv;
}

__global__ __launch_bounds__(256)
void split_w2_kernel(const float* __restrict__ w0, const float* __restrict__ w1,
                     const float* __restrict__ w2, const float* __restrict__ w3)
{
    int idx = blockIdx.x * blockDim.x + threadIdx.x;   // 0 .. 2M-1 (pairs)
    int e = idx * 2;
    int w = e >> 20;
    int off = e & 0xFFFFF;
    const float* src = (w == 0) ? w0 : (w == 1) ? w1 : (w == 2) ? w2 : w3;
    float2 v = *(const float2*)(src + off);
    uint32_t hv, lv;
    split2(v.x, v.y, hv, lv);
    ((uint32_t*)g_whi)[idx] = hv;
    ((uint32_t*)g_wlo)[idx] = lv;
}

// ---------------------------------------------------------------------------
// mma.sync split-bf16 GEMM with cp.async 2-stage double buffering.
// CTA tile 128x128, K-chunk 32, 8 warps 4(m)x2(n).
// Dynamic smem: 2 stages x [Ah|Al|Wh|Wl], each 128*PADK bf16.
// MODE 0: A = x split, W/bias by n>>10 (Wq/Wk/Wv).
//         w<2 -> fp32 g_q/g_k [B,H,T,Dh];  w==2 -> bf16 split g_vhi/g_vlo
// MODE 1: A = attn split, W = slot 3 (Wo), bias b0, out -> [M,1024] fp32
// ---------------------------------------------------------------------------
#define PADK 40   // bf16 per smem row (32 data + 8 pad); 80B stride
#define GARR (128 * PADK * 2)        // 10240 B per array
#define GSTG (4 * GARR)              // 40960 B per stage
#define GSMEM (2 * GSTG)             // 81920 B total

template <int MODE>
__global__ __launch_bounds__(256, 2)
void gemm_mma(const __nv_bfloat16* __restrict__ Ahi,
              const __nv_bfloat16* __restrict__ Alo,
              const float* __restrict__ b0, const float* __restrict__ b1,
              const float* __restrict__ b2, float* __restrict__ out)
{
    extern __shared__ char dsm[];
    const uint32_t sbase = smem_u32(dsm);

    const int tid = threadIdx.x;
    const int lane = tid & 31, wid = tid >> 5;
    const int m0 = blockIdx.y * 128;
    const int n_base = blockIdx.x * 128;
    const int w = (MODE == 0) ? (n_base >> 10) : 3;
    const int n_loc0 = (MODE == 0) ? (n_base & 1023) : n_base;
    const int warp_m = wid >> 1;
    const int warp_n = wid & 1;

    const int lrow = tid >> 1;
    const int lseg = (tid & 1) * 16;
    const __nv_bfloat16* pAh = Ahi + (size_t)(m0 + lrow) * DM + lseg;
    const __nv_bfloat16* pAl = Alo + (size_t)(m0 + lrow) * DM + lseg;
    const __nv_bfloat16* pWh = g_whi + ((size_t)w << 20) + (size_t)(n_loc0 + lrow) * DM + lseg;
    const __nv_bfloat16* pWl = g_wlo + ((size_t)w << 20) + (size_t)(n_loc0 + lrow) * DM + lseg;

    const uint32_t st_off = lrow * (PADK * 2) + lseg * 2;

    const int j = lane >> 3, r = lane & 7;
    const int mA = (j & 1) * 8 + r;
    const int kA = (j >> 1) * 8;
    const int nB = (j >> 1) * 8 + r;
    const int kB = (j & 1) * 8;

    float acc[2][8][4];
    #pragma unroll
    for (int i = 0; i < 2; i++)
        #pragma unroll
        for (int t = 0; t < 8; t++)
            #pragma unroll
            for (int e = 0; e < 4; e++) acc[i][t][e] = 0.0f;

    auto PF = [&](int c, int s) {
        uint32_t b = sbase + s * GSTG + st_off;
        const char* a  = (const char*)(pAh + c * 32);
        const char* l  = (const char*)(pAl + c * 32);
        const char* h  = (const char*)(pWh + c * 32);
        const char* w2 = (const char*)(pWl + c * 32);
        cp16(b,                  a);   cp16(b + 16,              a + 16);
        cp16(b + GARR,           l);   cp16(b + GARR + 16,       l + 16);
        cp16(b + 2 * GARR,       h);   cp16(b + 2 * GARR + 16,   h + 16);
        cp16(b + 3 * GARR,       w2);  cp16(b + 3 * GARR + 16,   w2 + 16);
    };

    PF(0, 0); cp_commit();

    for (int c = 0; c < 32; c++) {
        const int cur = c & 1;
        if (c + 1 < 32) { PF(c + 1, cur ^ 1); cp_commit(); cp_wait1(); }
        else            { cp_wait0(); }
        __syncthreads();

        const uint32_t bAh = sbase + cur * GSTG;
        const uint32_t bAl = bAh + GARR;
        const uint32_t bWh = bAh + 2 * GARR;
        const uint32_t bWl = bAh + 3 * GARR;

        #pragma unroll
        for (int kk = 0; kk < 2; kk++) {
            uint32_t ah[2][4], al[2][4];
            #pragma unroll
            for (int i = 0; i < 2; i++) {
                uint32_t roff = (uint32_t)(warp_m * 32 + i * 16 + mA) * (PADK * 2)
                              + (uint32_t)(kk * 16 + kA) * 2;
                ldsm_x4(ah[i], bAh + roff);
                ldsm_x4(al[i], bAl + roff);
            }
            #pragma unroll
            for (int p = 0; p < 4; p++) {
                uint32_t roff = (uint32_t)(warp_n * 64 + p * 16 + nB) * (PADK * 2)
                              + (uint32_t)(kk * 16 + kB) * 2;
                uint32_t wh[4], wl[4];
                ldsm_x4(wh, bWh + roff);
                ldsm_x4(wl, bWl + roff);
                #pragma unroll
                for (int i = 0; i < 2; i++) {
                    mma_bf16(acc[i][2*p],   ah[i], wh[0], wh[1]);
                    mma_bf16(acc[i][2*p+1], ah[i], wh[2], wh[3]);
                    mma_bf16(acc[i][2*p],   ah[i], wl[0], wl[1]);
                    mma_bf16(acc[i][2*p+1], ah[i], wl[2], wl[3]);
                    mma_bf16(acc[i][2*p],   al[i], wh[0], wh[1]);
                    mma_bf16(acc[i][2*p+1], al[i], wh[2], wh[3]);
                }
            }
        }
        __syncthreads();
    }

    const float* bias = (MODE == 0) ? ((w == 0) ? b0 : (w == 1) ? b1 : b2) : b0;
    const int gid = lane >> 2, tig2 = (lane & 3) * 2;

    #pragma unroll
    for (int i = 0; i < 2; i++) {
        const int mr0 = m0 + warp_m * 32 + i * 16 + gid;
        #pragma unroll
        for (int t = 0; t < 8; t++) {
            const int nl = n_loc0 + warp_n * 64 + t * 8 + tig2;
            const float bx = bias[nl], by = bias[nl + 1];
            float2 v0 = make_float2(acc[i][t][0] + bx, acc[i][t][1] + by);
            float2 v1 = make_float2(acc[i][t][2] + bx, acc[i][t][3] + by);
            if (MODE == 0) {
                const int h = nl >> 6, dh = nl & 63;
                if (w == 2) {
                    #pragma unroll
                    for (int hv = 0; hv < 2; hv++) {
                        const int m_ = mr0 + hv * 8;
                        const int b_ = m_ >> 11, tt = m_ & 2047;
                        size_t e = (((size_t)(b_ * NH + h) * TT) + tt) * DH + dh;
                        float vx = hv ? v1.x : v0.x, vy = hv ? v1.y : v0.y;
                        uint32_t hb, lb;
                        split2(vx, vy, hb, lb);
                        *(uint32_t*)&g_vhi[e] = hb;
                        *(uint32_t*)&g_vlo[e] = lb;
                    }
                } else {
                    float* dst = (w == 0) ? g_q : g_k;
                    {
                        const int b_ = mr0 >> 11, tt = mr0 & 2047;
                        *(float2*)&dst[(((size_t)(b_ * NH + h) * TT) + tt) * DH + dh] = v0;
                    }
                    {
                        const int m2 = mr0 + 8;
                        const int b_ = m2 >> 11, tt = m2 & 2047;
                        *(float2*)&dst[(((size_t)(b_ * NH + h) * TT) + tt) * DH + dh] = v1;
                    }
                }
            } else {
                *(float2*)&out[(size_t)mr0 * DM + nl]       = v0;
                *(float2*)&out[(size_t)(mr0 + 8) * DM + nl] = v1;
            }
        }
    }
}

// ---------------------------------------------------------------------------
// RoPE: trig table (one FP64 eval per (t,i)), then parallel fp32 apply+split.
// Matches JAX fp32 rounding: arg = fp32(t)*fp32(inv_freq); trig in double.
// ---------------------------------------------------------------------------
__global__ __launch_bounds__(256)
void trig_kernel()
{
    int idx = blockIdx.x * blockDim.x + threadIdx.x;   // 0 .. TT*32-1
    if (idx >= TT * 32) return;
    int i = idx & 31;
    int t = idx >> 5;
    double e   = -((double)(2 * i) / 64.0) * log(10000.0);
    float invf = (float)exp(e);
    float argf = (float)t * invf;
    double arg = (double)argf;
    g_cosv[idx] = (float)cos(arg);
    g_sinv[idx] = (float)sin(arg);
}

__global__ __launch_bounds__(256)
void rope_apply_kernel()
{
    int idx = blockIdx.x * blockDim.x + threadIdx.x;   // BH*TT*32
    int i  = idx & 31;
    int t  = (idx >> 5) & 2047;
    int bh = idx >> 16;
    float c = g_cosv[(t << 5) | i];
    float s = g_sinv[(t << 5) | i];

    size_t base = ((size_t)bh * TT + t) * DH;
    float q1 = g_q[base + i], q2 = g_q[base + i + 32];
    float rq1 = (q1 * c - q2 * s) * 0.125f;
    float rq2 = (q2 * c + q1 * s) * 0.125f;
    __nv_bfloat16 h;
    h = __float2bfloat16(rq1); g_qhi[base + i]      = h;
    g_qlo[base + i]      = __float2bfloat16(rq1 - __bfloat162float(h));
    h = __float2bfloat16(rq2); g_qhi[base + i + 32] = h;
    g_qlo[base + i + 32] = __float2bfloat16(rq2 - __bfloat162float(h));

    float k1 = g_k[base + i], k2 = g_k[base + i + 32];
    float rk1 = k1 * c - k2 * s;
    float rk2 = k2 * c + k1 * s;
    h = __float2bfloat16(rk1); g_khi[base + i]      = h;
    g_klo[base + i]      = __float2bfloat16(rk1 - __bfloat162float(h));
    h = __float2bfloat16(rk2); g_khi[base + i + 32] = h;
    g_klo[base + i + 32] = __float2bfloat16(rk2 - __bfloat162float(h));
}

// ---------------------------------------------------------------------------
// Flash attention on mma.sync with cp.async 2-stage K/V double buffering.
// Block: 128 threads (4 warps), 64 q-rows; warp owns 16 q-rows.
// Dynamic smem: 2 stages x [Kh|Kl|Vh|Vl], each 64*ASTR bf16.
// ---------------------------------------------------------------------------
#define ASTR 72   // bf16 per smem row (64 data + 8 pad); 144B stride
#define AARR (64 * ASTR * 2)         // 9216 B per array
#define ASTG (4 * AARR)              // 36864 B per stage
#define ASMEM (2 * ASTG)             // 73728 B total

__global__ __launch_bounds__(128)
void attn_mma_kernel()
{
    extern __shared__ char dsm[];
    const uint32_t sbase = smem_u32(dsm);

    const int bh = blockIdx.y;
    const int q0 = blockIdx.x * 64;
    const int tid = threadIdx.x;
    const int lane = tid & 31, wid = tid >> 5;
    const int j = lane >> 3, r = lane & 7;

    const size_t headoff = (size_t)bh * TT * DH;
    const __nv_bfloat16* pQh = g_qhi + headoff + (size_t)q0 * DH;
    const __nv_bfloat16* pQl = g_qlo + headoff + (size_t)q0 * DH;
    const __nv_bfloat16* pKh = g_khi + headoff;
    const __nv_bfloat16* pKl = g_klo + headoff;
    const __nv_bfloat16* pVh = g_vhi + headoff;
    const __nv_bfloat16* pVl = g_vlo + headoff;

    // tile-load mapping: 2 threads per row, 32 bf16 (64B) each
    const int lrow = tid >> 1, lhalf = (tid & 1) * 32;
    const uint32_t sm_off = lrow * (ASTR * 2) + lhalf * 2;

    auto PF = [&](int itj, int s) {     // K/V tile j0 = itj*64 -> stage s
        uint32_t b = sbase + s * ASTG + sm_off;
        const char* a = (const char*)(pKh + (size_t)(itj * 64 + lrow) * DH + lhalf);
        const char* c = (const char*)(pKl + (size_t)(itj * 64 + lrow) * DH + lhalf);
        const char* d = (const char*)(pVh + (size_t)(itj * 64 + lrow) * DH + lhalf);
        const char* e = (const char*)(pVl + (size_t)(itj * 64 + lrow) * DH + lhalf);
        #pragma unroll
        for (int s2 = 0; s2 < 4; s2++) {
            cp16(b + s2 * 16,            a + s2 * 16);
            cp16(b + AARR + s2 * 16,     c + s2 * 16);
            cp16(b + 2 * AARR + s2 * 16, d + s2 * 16);
            cp16(b + 3 * AARR + s2 * 16, e + s2 * 16);
        }
    };

    // prefetch first K/V tile into stage 0
    PF(0, 0); cp_commit();

    // stage 1's Kh/Kl region doubles as Q staging
    {
        char* qh = dsm + ASTG + sm_off;
        char* ql = dsm + ASTG + AARR + sm_off;
        const uint4* gh = (const uint4*)(pQh + (size_t)lrow * DH + lhalf);
        const uint4* gl = (const uint4*)(pQl + (size_t)lrow * DH + lhalf);
        #pragma unroll
        for (int s2 = 0; s2 < 4; s2++) {
            *(uint4*)(qh + s2 * 16) = gh[s2];
            *(uint4*)(ql + s2 * 16) = gl[s2];
        }
    }
    __syncthreads();

    uint32_t qh[4][4], ql[4][4];
    {
        const int mA = (j & 1) * 8 + r, kA = (j >> 1) * 8;
        const uint32_t bQh = sbase + ASTG, bQl = bQh + AARR;
        #pragma unroll
        for (int kk = 0; kk < 4; kk++) {
            uint32_t off = (uint32_t)(wid * 16 + mA) * (ASTR * 2)
                         + (uint32_t)(kk * 16 + kA) * 2;
            ldsm_x4(qh[kk], bQh + off);
            ldsm_x4(ql[kk], bQl + off);
        }
    }
    __syncthreads();   // Q extracted; stage 1 free for prefetch

    const int nB = (j >> 1) * 8 + r, kB = (j & 1) * 8;   // K ldsm lanes
    const int vk = lane & 15, vn8 = (lane >> 4) * 8;     // V trans lanes

    float m_r[2] = {-INFINITY, -INFINITY};
    float l_r[2] = {0.0f, 0.0f};
    float oacc[8][4];
    #pragma unroll
    for (int t = 0; t < 8; t++)
        #pragma unroll
        for (int e = 0; e < 4; e++) oacc[t][e] = 0.0f;

    for (int it = 0; it < 32; it++) {
        const int cur = it & 1;
        if (it + 1 < 32) { PF(it + 1, cur ^ 1); cp_commit(); cp_wait1(); }
        else             { cp_wait0(); }
        __syncthreads();

        const uint32_t bKh = sbase + cur * ASTG;
        const uint32_t bKl = bKh + AARR;
        const uint32_t bVh = bKh + 2 * AARR;
        const uint32_t bVl = bKh + 3 * AARR;

        // ---- S = Q K^T (3 split combos) ----
        float sacc[8][4];
        #pragma unroll
        for (int t = 0; t < 8; t++)
            #pragma unroll
            for (int e = 0; e < 4; e++) sacc[t][e] = 0.0f;

        #pragma unroll
        for (int kk = 0; kk < 4; kk++) {
            #pragma unroll
            for (int p = 0; p < 4; p++) {
                uint32_t off = (uint32_t)(p * 16 + nB) * (ASTR * 2)
                             + (uint32_t)(kk * 16 + kB) * 2;
                uint32_t kh4[4], kl4[4];
                ldsm_x4(kh4, bKh + off);
                ldsm_x4(kl4, bKl + off);
                mma_bf16(sacc[2*p],   qh[kk], kh4[0], kh4[1]);
                mma_bf16(sacc[2*p+1], qh[kk], kh4[2], kh4[3]);
                mma_bf16(sacc[2*p],   qh[kk], kl4[0], kl4[1]);
                mma_bf16(sacc[2*p+1], qh[kk], kl4[2], kl4[3]);
                mma_bf16(sacc[2*p],   ql[kk], kh4[0], kh4[1]);
                mma_bf16(sacc[2*p+1], ql[kk], kh4[2], kh4[3]);
            }
        }

        // ---- online softmax (rows gid, gid+8; quad lanes share a row) ----
        float mx0 = -INFINITY, mx1 = -INFINITY;
        #pragma unroll
        for (int t = 0; t < 8; t++) {
            mx0 = fmaxf(mx0, fmaxf(sacc[t][0], sacc[t][1]));
            mx1 = fmaxf(mx1, fmaxf(sacc[t][2], sacc[t][3]));
        }
        #pragma unroll
        for (int off = 1; off < 4; off <<= 1) {
            mx0 = fmaxf(mx0, __shfl_xor_sync(0xffffffffu, mx0, off));
            mx1 = fmaxf(mx1, __shfl_xor_sync(0xffffffffu, mx1, off));
        }
        float mn0 = fmaxf(m_r[0], mx0), mn1 = fmaxf(m_r[1], mx1);
        float cr0 = __expf(m_r[0] - mn0), cr1 = __expf(m_r[1] - mn1);
        float rs0 = 0.0f, rs1 = 0.0f;
        #pragma unroll
        for (int t = 0; t < 8; t++) {
            sacc[t][0] = __expf(sacc[t][0] - mn0);
            sacc[t][1] = __expf(sacc[t][1] - mn0);
            sacc[t][2] = __expf(sacc[t][2] - mn1);
            sacc[t][3] = __expf(sacc[t][3] - mn1);
            rs0 += sacc[t][0] + sacc[t][1];
            rs1 += sacc[t][2] + sacc[t][3];
        }
        #pragma unroll
        for (int off = 1; off < 4; off <<= 1) {
            rs0 += __shfl_xor_sync(0xffffffffu, rs0, off);
            rs1 += __shfl_xor_sync(0xffffffffu, rs1, off);
        }
        l_r[0] = l_r[0] * cr0 + rs0;  m_r[0] = mn0;
        l_r[1] = l_r[1] * cr1 + rs1;  m_r[1] = mn1;
        #pragma unroll
        for (int t = 0; t < 8; t++) {
            oacc[t][0] *= cr0;  oacc[t][1] *= cr0;
            oacc[t][2] *= cr1;  oacc[t][3] *= cr1;
        }

        // ---- O += P V (P split in regs, V split via ldmatrix.trans) ----
        #pragma unroll
        for (int kc = 0; kc < 4; kc++) {
            uint32_t phi[4], plo[4];
            split2(sacc[2*kc][0],   sacc[2*kc][1],   phi[0], plo[0]);
            split2(sacc[2*kc][2],   sacc[2*kc][3],   phi[1], plo[1]);
            split2(sacc[2*kc+1][0], sacc[2*kc+1][1], phi[2], plo[2]);
            split2(sacc[2*kc+1][2], sacc[2*kc+1][3], phi[3], plo[3]);
            #pragma unroll
            for (int p = 0; p < 4; p++) {
                uint32_t off = (uint32_t)(kc * 16 + vk) * (ASTR * 2)
                             + (uint32_t)(p * 16 + vn8) * 2;
                uint32_t vh4[4], vl4[4];
                ldsm_x4_t(vh4, bVh + off);
                ldsm_x4_t(vl4, bVl + off);
                mma_bf16(oacc[2*p],   phi, vh4[0], vh4[1]);
                mma_bf16(oacc[2*p+1], phi, vh4[2], vh4[3]);
                mma_bf16(oacc[2*p],   phi, vl4[0], vl4[1]);
                mma_bf16(oacc[2*p+1], phi, vl4[2], vl4[3]);
                mma_bf16(oacc[2*p],   plo, vh4[0], vh4[1]);
                mma_bf16(oacc[2*p+1], plo, vh4[2], vh4[3]);
            }
        }
        __syncthreads();
    }

    // ---- epilogue: normalize, split to bf16 hi/lo, write [B,T,D] ----
    const int gid = lane >> 2, tg2 = (lane & 3) * 2;
    const float inv0 = 1.0f / l_r[0], inv1 = 1.0f / l_r[1];
    const int b_ = bh >> 4, h = bh & 15;
    const int row0 = q0 + wid * 16 + gid;
    uint32_t* ahi32 = (uint32_t*)g_ahi;
    uint32_t* alo32 = (uint32_t*)g_alo;

    #pragma unroll
    for (int t = 0; t < 8; t++) {
        const int col = h * 64 + t * 8 + tg2;
        uint32_t hv, lv;
        split2(oacc[t][0] * inv0, oacc[t][1] * inv0, hv, lv);
        size_t e0 = (((size_t)(b_ * TT + row0)) * DM + col) >> 1;
        ahi32[e0] = hv;  alo32[e0] = lv;
        split2(oacc[t][2] * inv1, oacc[t][3] * inv1, hv, lv);
        size_t e1 = (((size_t)(b_ * TT + row0 + 8)) * DM + col) >> 1;
        ahi32[e1] = hv;  alo32[e1] = lv;
    }
}

// ---------------------------------------------------------------------------
extern "C" void kernel_launch(void* const* d_in, const int* in_sizes, int n_in,
                              void* d_out, int out_size)
{
    const float* x  = (const float*)d_in[0];
    const float* Wq = (const float*)d_in[1];
    const float* bq = (const float*)d_in[2];
    const float* Wk = (const float*)d_in[3];
    const float* bk = (const float*)d_in[4];
    const float* Wv = (const float*)d_in[5];
    const float* bv = (const float*)d_in[6];
    const float* Wo = (const float*)d_in[7];
    const float* bo = (const float*)d_in[8];
    float* out = (float*)d_out;

    cudaFuncSetAttribute(gemm_mma<0>, cudaFuncAttributeMaxDynamicSharedMemorySize, GSMEM);
    cudaFuncSetAttribute(gemm_mma<1>, cudaFuncAttributeMaxDynamicSharedMemorySize, GSMEM);
    cudaFuncSetAttribute(attn_mma_kernel, cudaFuncAttributeMaxDynamicSharedMemorySize, ASMEM);

    __nv_bfloat16 *xhi, *xlo, *ahi, *alo;
    cudaGetSymbolAddress((void**)&xhi, g_xhi);
    cudaGetSymbolAddress((void**)&xlo, g_xlo);
    cudaGetSymbolAddress((void**)&ahi, g_ahi);
    cudaGetSymbolAddress((void**)&alo, g_alo);

    // 0) split x and weights into bf16 hi/lo (vectorized) + trig table
    split2_kernel<<<(BT * DM / 2 + 255) / 256, 256>>>(x, xhi, xlo, BT * DM / 2);
    split_w2_kernel<<<(4 * DM * DM / 2 + 255) / 256, 256>>>(Wq, Wk, Wv, Wo);
    trig_kernel<<<(TT * 32 + 255) / 256, 256>>>();

    // 1) QKV projection: q,k -> fp32 [B,H,T,Dh]; v -> bf16 split
    dim3 g1(3072 / 128, BT / 128);
    gemm_mma<0><<<g1, 256, GSMEM>>>(xhi, xlo, bq, bk, bv, nullptr);

    // 2) RoPE apply + scale + bf16 split for q,k
    rope_apply_kernel<<<(BH * TT * 32) / 256, 256>>>();

    // 3) flash attention (mma.sync + cp.async) -> g_ahi/g_alo [B,T,D]
    dim3 g3(TT / 64, BH);
    attn_mma_kernel<<<g3, 128, ASMEM>>>();

    // 4) output projection -> d_out
    dim3 g4(DM / 128, BT / 128);
    gemm_mma<1><<<g4, 256, GSMEM>>>(ahi, alo, bo, nullptr, nullptr, out);
}

// round 10
// speedup vs baseline: 2.8500x; 1.0220x over previous
#include <cuda_runtime.h>
#include <cuda_bf16.h>
#include <math.h>
#include <stdint.h>

// Problem constants
#define BB 2
#define TT 2048
#define DM 1024
#define NH 16
#define DH 64
#define BT (BB*TT)          // 4096
#define BH (BB*NH)          // 32

// Scratch (device globals; no allocation allowed)
__device__ float g_q[BH * TT * DH];     // [B,H,T,Dh] fp32 (pre-rope)
__device__ float g_k[BH * TT * DH];
__device__ float g_cosv[TT * 32];
__device__ float g_sinv[TT * 32];

// bf16 hi/lo split buffers
__device__ __nv_bfloat16 g_xhi[BT * DM];
__device__ __nv_bfloat16 g_xlo[BT * DM];
__device__ __nv_bfloat16 g_whi[4 * DM * DM];   // Wq,Wk,Wv,Wo
__device__ __nv_bfloat16 g_wlo[4 * DM * DM];
__device__ __nv_bfloat16 g_qhi[BH * TT * DH];  // roped, scaled by 0.125
__device__ __nv_bfloat16 g_qlo[BH * TT * DH];
__device__ __nv_bfloat16 g_khi[BH * TT * DH];  // roped
__device__ __nv_bfloat16 g_klo[BH * TT * DH];
__device__ __nv_bfloat16 g_vhi[BH * TT * DH];
__device__ __nv_bfloat16 g_vlo[BH * TT * DH];
__device__ __nv_bfloat16 g_ahi[BT * DM];       // attn output split [B,T,D]
__device__ __nv_bfloat16 g_alo[BT * DM];

// ---------------------------------------------------------------------------
// PTX helpers (plain sm_103 target: ldmatrix + mma.sync + cp.async)
// ---------------------------------------------------------------------------
__device__ __forceinline__ uint32_t smem_u32(const void* p) {
    uint32_t a;
    asm("{ .reg .u64 t; cvta.to.shared.u64 t, %1; cvt.u32.u64 %0, t; }"
        : "=r"(a) : "l"(p));
    return a;
}

__device__ __forceinline__ void ldsm_x4(uint32_t* r, uint32_t addr) {
    asm volatile("ldmatrix.sync.aligned.m8n8.x4.shared.b16 {%0,%1,%2,%3}, [%4];"
                 : "=r"(r[0]), "=r"(r[1]), "=r"(r[2]), "=r"(r[3]) : "r"(addr));
}

__device__ __forceinline__ void ldsm_x4_t(uint32_t* r, uint32_t addr) {
    asm volatile("ldmatrix.sync.aligned.m8n8.x4.trans.shared.b16 {%0,%1,%2,%3}, [%4];"
                 : "=r"(r[0]), "=r"(r[1]), "=r"(r[2]), "=r"(r[3]) : "r"(addr));
}

__device__ __forceinline__ void mma_bf16(float* d, const uint32_t* a,
                                         uint32_t b0, uint32_t b1) {
    asm volatile(
        "mma.sync.aligned.m16n8k16.row.col.f32.bf16.bf16.f32 "
        "{%0,%1,%2,%3}, {%4,%5,%6,%7}, {%8,%9}, {%0,%1,%2,%3};"
        : "+f"(d[0]), "+f"(d[1]), "+f"(d[2]), "+f"(d[3])
        : "r"(a[0]), "r"(a[1]), "r"(a[2]), "r"(a[3]), "r"(b0), "r"(b1));
}

__device__ __forceinline__ void cp16(uint32_t s, const void* g) {
    asm volatile("cp.async.cg.shared.global [%0], [%1], 16;" :: "r"(s), "l"(g));
}
__device__ __forceinline__ void cp_commit() {
    asm volatile("cp.async.commit_group;" ::: "memory");
}
__device__ __forceinline__ void cp_wait0() {
    asm volatile("cp.async.wait_group 0;" ::: "memory");
}

__device__ __forceinline__ uint32_t pack_bf16x2(float x, float y) {
    __nv_bfloat162 h = __floats2bfloat162_rn(x, y);
    return *(uint32_t*)&h;
}

// split a float pair into bf16 hi pair + bf16 lo (residual) pair
__device__ __forceinline__ void split2(float x, float y,
                                       uint32_t& hv, uint32_t& lv) {
    __nv_bfloat16 h0 = __float2bfloat16(x);
    __nv_bfloat16 h1 = __float2bfloat16(y);
    hv = ((uint32_t)*(uint16_t*)&h1 << 16) | *(uint16_t*)&h0;
    lv = pack_bf16x2(x - __bfloat162float(h0), y - __bfloat162float(h1));
}

// ---------------------------------------------------------------------------
// fp32 -> bf16 hi/lo split kernels (vectorized: 2 elements / thread)
// ---------------------------------------------------------------------------
__global__ __launch_bounds__(256)
void split2_kernel(const float* __restrict__ src,
                   __nv_bfloat16* __restrict__ hi,
                   __nv_bfloat16* __restrict__ lo, int n2)
{
    int idx = blockIdx.x * blockDim.x + threadIdx.x;
    if (idx >= n2) return;
    float2 v = ((const float2*)src)[idx];
    uint32_t hv, lv;
    split2(v.x, v.y, hv, lv);
    ((uint32_t*)hi)[idx] = hv;
    ((uint32_t*)lo)[idx] = lv;
}

__global__ __launch_bounds__(256)
void split_w2_kernel(const float* __restrict__ w0, const float* __restrict__ w1,
                     const float* __restrict__ w2, const float* __restrict__ w3)
{
    int idx = blockIdx.x * blockDim.x + threadIdx.x;   // 0 .. 2M-1 (pairs)
    int e = idx * 2;
    int w = e >> 20;
    int off = e & 0xFFFFF;
    const float* src = (w == 0) ? w0 : (w == 1) ? w1 : (w == 2) ? w2 : w3;
    float2 v = *(const float2*)(src + off);
    uint32_t hv, lv;
    split2(v.x, v.y, hv, lv);
    ((uint32_t*)g_whi)[idx] = hv;
    ((uint32_t*)g_wlo)[idx] = lv;
}

// ---------------------------------------------------------------------------
// mma.sync split-bf16 GEMM, cp.async 2-stage, SINGLE sync per K-chunk:
//   wait(stage c) -> sync -> prefetch(c+1 into other stage) -> compute(c)
// The one barrier both publishes stage c and protects stage c^1 reuse.
// CTA tile 128x128, K-chunk 32, 8 warps 4(m)x2(n).
// MODE 0: A = x split, W/bias by n>>10 (Wq/Wk/Wv).
//         w<2 -> fp32 g_q/g_k [B,H,T,Dh];  w==2 -> bf16 split g_vhi/g_vlo
// MODE 1: A = attn split, W = slot 3 (Wo), bias b0, out -> [M,1024] fp32
// ---------------------------------------------------------------------------
#define PADK 40   // bf16 per smem row (32 data + 8 pad); 80B stride
#define GARR (128 * PADK * 2)        // 10240 B per array
#define GSTG (4 * GARR)              // 40960 B per stage
#define GSMEM (2 * GSTG)             // 81920 B total

template <int MODE>
__global__ __launch_bounds__(256, 2)
void gemm_mma(const __nv_bfloat16* __restrict__ Ahi,
              const __nv_bfloat16* __restrict__ Alo,
              const float* __restrict__ b0, const float* __restrict__ b1,
              const float* __restrict__ b2, float* __restrict__ out)
{
    extern __shared__ char dsm[];
    const uint32_t sbase = smem_u32(dsm);

    const int tid = threadIdx.x;
    const int lane = tid & 31, wid = tid >> 5;
    const int m0 = blockIdx.y * 128;
    const int n_base = blockIdx.x * 128;
    const int w = (MODE == 0) ? (n_base >> 10) : 3;
    const int n_loc0 = (MODE == 0) ? (n_base & 1023) : n_base;
    const int warp_m = wid >> 1;
    const int warp_n = wid & 1;

    const int lrow = tid >> 1;
    const int lseg = (tid & 1) * 16;
    const __nv_bfloat16* pAh = Ahi + (size_t)(m0 + lrow) * DM + lseg;
    const __nv_bfloat16* pAl = Alo + (size_t)(m0 + lrow) * DM + lseg;
    const __nv_bfloat16* pWh = g_whi + ((size_t)w << 20) + (size_t)(n_loc0 + lrow) * DM + lseg;
    const __nv_bfloat16* pWl = g_wlo + ((size_t)w << 20) + (size_t)(n_loc0 + lrow) * DM + lseg;

    const uint32_t st_off = lrow * (PADK * 2) + lseg * 2;

    const int j = lane >> 3, r = lane & 7;
    const int mA = (j & 1) * 8 + r;
    const int kA = (j >> 1) * 8;
    const int nB = (j >> 1) * 8 + r;
    const int kB = (j & 1) * 8;

    float acc[2][8][4];
    #pragma unroll
    for (int i = 0; i < 2; i++)
        #pragma unroll
        for (int t = 0; t < 8; t++)
            #pragma unroll
            for (int e = 0; e < 4; e++) acc[i][t][e] = 0.0f;

    auto PF = [&](int c, int s) {
        uint32_t b = sbase + s * GSTG + st_off;
        const char* a  = (const char*)(pAh + c * 32);
        const char* l  = (const char*)(pAl + c * 32);
        const char* h  = (const char*)(pWh + c * 32);
        const char* w2 = (const char*)(pWl + c * 32);
        cp16(b,                  a);   cp16(b + 16,              a + 16);
        cp16(b + GARR,           l);   cp16(b + GARR + 16,       l + 16);
        cp16(b + 2 * GARR,       h);   cp16(b + 2 * GARR + 16,   h + 16);
        cp16(b + 3 * GARR,       w2);  cp16(b + 3 * GARR + 16,   w2 + 16);
    };

    PF(0, 0); cp_commit();

    for (int c = 0; c < 32; c++) {
        const int cur = c & 1;
        cp_wait0();          // stage cur's data has arrived
        __syncthreads();     // publish stage cur; all reads of stage cur^1 done
        if (c + 1 < 32) { PF(c + 1, cur ^ 1); cp_commit(); }

        const uint32_t bAh = sbase + cur * GSTG;
        const uint32_t bAl = bAh + GARR;
        const uint32_t bWh = bAh + 2 * GARR;
        const uint32_t bWl = bAh + 3 * GARR;

        #pragma unroll
        for (int kk = 0; kk < 2; kk++) {
            uint32_t ah[2][4], al[2][4];
            #pragma unroll
            for (int i = 0; i < 2; i++) {
                uint32_t roff = (uint32_t)(warp_m * 32 + i * 16 + mA) * (PADK * 2)
                              + (uint32_t)(kk * 16 + kA) * 2;
                ldsm_x4(ah[i], bAh + roff);
                ldsm_x4(al[i], bAl + roff);
            }
            #pragma unroll
            for (int p = 0; p < 4; p++) {
                uint32_t roff = (uint32_t)(warp_n * 64 + p * 16 + nB) * (PADK * 2)
                              + (uint32_t)(kk * 16 + kB) * 2;
                uint32_t wh[4], wl[4];
                ldsm_x4(wh, bWh + roff);
                ldsm_x4(wl, bWl + roff);
                #pragma unroll
                for (int i = 0; i < 2; i++) {
                    mma_bf16(acc[i][2*p],   ah[i], wh[0], wh[1]);
                    mma_bf16(acc[i][2*p+1], ah[i], wh[2], wh[3]);
                    mma_bf16(acc[i][2*p],   ah[i], wl[0], wl[1]);
                    mma_bf16(acc[i][2*p+1], ah[i], wl[2], wl[3]);
                    mma_bf16(acc[i][2*p],   al[i], wh[0], wh[1]);
                    mma_bf16(acc[i][2*p+1], al[i], wh[2], wh[3]);
                }
            }
        }
    }

    const float* bias = (MODE == 0) ? ((w == 0) ? b0 : (w == 1) ? b1 : b2) : b0;
    const int gid = lane >> 2, tig2 = (lane & 3) * 2;

    #pragma unroll
    for (int i = 0; i < 2; i++) {
        const int mr0 = m0 + warp_m * 32 + i * 16 + gid;
        #pragma unroll
        for (int t = 0; t < 8; t++) {
            const int nl = n_loc0 + warp_n * 64 + t * 8 + tig2;
            const float bx = bias[nl], by = bias[nl + 1];
            float2 v0 = make_float2(acc[i][t][0] + bx, acc[i][t][1] + by);
            float2 v1 = make_float2(acc[i][t][2] + bx, acc[i][t][3] + by);
            if (MODE == 0) {
                const int h = nl >> 6, dh = nl & 63;
                if (w == 2) {
                    #pragma unroll
                    for (int hv = 0; hv < 2; hv++) {
                        const int m_ = mr0 + hv * 8;
                        const int b_ = m_ >> 11, tt = m_ & 2047;
                        size_t e = (((size_t)(b_ * NH + h) * TT) + tt) * DH + dh;
                        float vx = hv ? v1.x : v0.x, vy = hv ? v1.y : v0.y;
                        uint32_t hb, lb;
                        split2(vx, vy, hb, lb);
                        *(uint32_t*)&g_vhi[e] = hb;
                        *(uint32_t*)&g_vlo[e] = lb;
                    }
                } else {
                    float* dst = (w == 0) ? g_q : g_k;
                    {
                        const int b_ = mr0 >> 11, tt = mr0 & 2047;
                        *(float2*)&dst[(((size_t)(b_ * NH + h) * TT) + tt) * DH + dh] = v0;
                    }
                    {
                        const int m2 = mr0 + 8;
                        const int b_ = m2 >> 11, tt = m2 & 2047;
                        *(float2*)&dst[(((size_t)(b_ * NH + h) * TT) + tt) * DH + dh] = v1;
                    }
                }
            } else {
                *(float2*)&out[(size_t)mr0 * DM + nl]       = v0;
                *(float2*)&out[(size_t)(mr0 + 8) * DM + nl] = v1;
            }
        }
    }
}

// ---------------------------------------------------------------------------
// RoPE: trig table (one FP64 eval per (t,i)), then parallel fp32 apply+split.
// Matches JAX fp32 rounding: arg = fp32(t)*fp32(inv_freq); trig in double.
// ---------------------------------------------------------------------------
__global__ __launch_bounds__(256)
void trig_kernel()
{
    int idx = blockIdx.x * blockDim.x + threadIdx.x;   // 0 .. TT*32-1
    if (idx >= TT * 32) return;
    int i = idx & 31;
    int t = idx >> 5;
    double e   = -((double)(2 * i) / 64.0) * log(10000.0);
    float invf = (float)exp(e);
    float argf = (float)t * invf;
    double arg = (double)argf;
    g_cosv[idx] = (float)cos(arg);
    g_sinv[idx] = (float)sin(arg);
}

__global__ __launch_bounds__(256)
void rope_apply_kernel()
{
    int idx = blockIdx.x * blockDim.x + threadIdx.x;   // BH*TT*32
    int i  = idx & 31;
    int t  = (idx >> 5) & 2047;
    int bh = idx >> 16;
    float c = g_cosv[(t << 5) | i];
    float s = g_sinv[(t << 5) | i];

    size_t base = ((size_t)bh * TT + t) * DH;
    float q1 = g_q[base + i], q2 = g_q[base + i + 32];
    float rq1 = (q1 * c - q2 * s) * 0.125f;
    float rq2 = (q2 * c + q1 * s) * 0.125f;
    __nv_bfloat16 h;
    h = __float2bfloat16(rq1); g_qhi[base + i]      = h;
    g_qlo[base + i]      = __float2bfloat16(rq1 - __bfloat162float(h));
    h = __float2bfloat16(rq2); g_qhi[base + i + 32] = h;
    g_qlo[base + i + 32] = __float2bfloat16(rq2 - __bfloat162float(h));

    float k1 = g_k[base + i], k2 = g_k[base + i + 32];
    float rk1 = k1 * c - k2 * s;
    float rk2 = k2 * c + k1 * s;
    h = __float2bfloat16(rk1); g_khi[base + i]      = h;
    g_klo[base + i]      = __float2bfloat16(rk1 - __bfloat162float(h));
    h = __float2bfloat16(rk2); g_khi[base + i + 32] = h;
    g_klo[base + i + 32] = __float2bfloat16(rk2 - __bfloat162float(h));
}

// ---------------------------------------------------------------------------
// Flash attention on mma.sync, cp.async 2-stage, single sync per K/V tile
// (same wait -> sync -> prefetch -> compute ordering as gemm_mma).
// Block: 128 threads (4 warps), 64 q-rows; warp owns 16 q-rows.
// ---------------------------------------------------------------------------
#define ASTR 72   // bf16 per smem row (64 data + 8 pad); 144B stride
#define AARR (64 * ASTR * 2)         // 9216 B per array
#define ASTG (4 * AARR)              // 36864 B per stage
#define ASMEM (2 * ASTG)             // 73728 B total

__global__ __launch_bounds__(128)
void attn_mma_kernel()
{
    extern __shared__ char dsm[];
    const uint32_t sbase = smem_u32(dsm);

    const int bh = blockIdx.y;
    const int q0 = blockIdx.x * 64;
    const int tid = threadIdx.x;
    const int lane = tid & 31, wid = tid >> 5;
    const int j = lane >> 3, r = lane & 7;

    const size_t headoff = (size_t)bh * TT * DH;
    const __nv_bfloat16* pQh = g_qhi + headoff + (size_t)q0 * DH;
    const __nv_bfloat16* pQl = g_qlo + headoff + (size_t)q0 * DH;
    const __nv_bfloat16* pKh = g_khi + headoff;
    const __nv_bfloat16* pKl = g_klo + headoff;
    const __nv_bfloat16* pVh = g_vhi + headoff;
    const __nv_bfloat16* pVl = g_vlo + headoff;

    // tile-load mapping: 2 threads per row, 32 bf16 (64B) each
    const int lrow = tid >> 1, lhalf = (tid & 1) * 32;
    const uint32_t sm_off = lrow * (ASTR * 2) + lhalf * 2;

    auto PF = [&](int itj, int s) {     // K/V tile j0 = itj*64 -> stage s
        uint32_t b = sbase + s * ASTG + sm_off;
        const char* a = (const char*)(pKh + (size_t)(itj * 64 + lrow) * DH + lhalf);
        const char* c = (const char*)(pKl + (size_t)(itj * 64 + lrow) * DH + lhalf);
        const char* d = (const char*)(pVh + (size_t)(itj * 64 + lrow) * DH + lhalf);
        const char* e = (const char*)(pVl + (size_t)(itj * 64 + lrow) * DH + lhalf);
        #pragma unroll
        for (int s2 = 0; s2 < 4; s2++) {
            cp16(b + s2 * 16,            a + s2 * 16);
            cp16(b + AARR + s2 * 16,     c + s2 * 16);
            cp16(b + 2 * AARR + s2 * 16, d + s2 * 16);
            cp16(b + 3 * AARR + s2 * 16, e + s2 * 16);
        }
    };

    // prefetch first K/V tile into stage 0
    PF(0, 0); cp_commit();

    // stage 1's Kh/Kl region doubles as Q staging
    {
        char* qh = dsm + ASTG + sm_off;
        char* ql = dsm + ASTG + AARR + sm_off;
        const uint4* gh = (const uint4*)(pQh + (size_t)lrow * DH + lhalf);
        const uint4* gl = (const uint4*)(pQl + (size_t)lrow * DH + lhalf);
        #pragma unroll
        for (int s2 = 0; s2 < 4; s2++) {
            *(uint4*)(qh + s2 * 16) = gh[s2];
            *(uint4*)(ql + s2 * 16) = gl[s2];
        }
    }
    __syncthreads();

    uint32_t qh[4][4], ql[4][4];
    {
        const int mA = (j & 1) * 8 + r, kA = (j >> 1) * 8;
        const uint32_t bQh = sbase + ASTG, bQl = bQh + AARR;
        #pragma unroll
        for (int kk = 0; kk < 4; kk++) {
            uint32_t off = (uint32_t)(wid * 16 + mA) * (ASTR * 2)
                         + (uint32_t)(kk * 16 + kA) * 2;
            ldsm_x4(qh[kk], bQh + off);
            ldsm_x4(ql[kk], bQl + off);
        }
    }

    const int nB = (j >> 1) * 8 + r, kB = (j & 1) * 8;   // K ldsm lanes
    const int vk = lane & 15, vn8 = (lane >> 4) * 8;     // V trans lanes

    float m_r[2] = {-INFINITY, -INFINITY};
    float l_r[2] = {0.0f, 0.0f};
    float oacc[8][4];
    #pragma unroll
    for (int t = 0; t < 8; t++)
        #pragma unroll
        for (int e = 0; e < 4; e++) oacc[t][e] = 0.0f;

    for (int it = 0; it < 32; it++) {
        const int cur = it & 1;
        cp_wait0();          // stage cur's K/V arrived
        __syncthreads();     // publish; all reads of stage cur^1 done
                             // (for it==0 this also covers the Q extraction)
        if (it + 1 < 32) { PF(it + 1, cur ^ 1); cp_commit(); }

        const uint32_t bKh = sbase + cur * ASTG;
        const uint32_t bKl = bKh + AARR;
        const uint32_t bVh = bKh + 2 * AARR;
        const uint32_t bVl = bKh + 3 * AARR;

        // ---- S = Q K^T (3 split combos) ----
        float sacc[8][4];
        #pragma unroll
        for (int t = 0; t < 8; t++)
            #pragma unroll
            for (int e = 0; e < 4; e++) sacc[t][e] = 0.0f;

        #pragma unroll
        for (int kk = 0; kk < 4; kk++) {
            #pragma unroll
            for (int p = 0; p < 4; p++) {
                uint32_t off = (uint32_t)(p * 16 + nB) * (ASTR * 2)
                             + (uint32_t)(kk * 16 + kB) * 2;
                uint32_t kh4[4], kl4[4];
                ldsm_x4(kh4, bKh + off);
                ldsm_x4(kl4, bKl + off);
                mma_bf16(sacc[2*p],   qh[kk], kh4[0], kh4[1]);
                mma_bf16(sacc[2*p+1], qh[kk], kh4[2], kh4[3]);
                mma_bf16(sacc[2*p],   qh[kk], kl4[0], kl4[1]);
                mma_bf16(sacc[2*p+1], qh[kk], kl4[2], kl4[3]);
                mma_bf16(sacc[2*p],   ql[kk], kh4[0], kh4[1]);
                mma_bf16(sacc[2*p+1], ql[kk], kh4[2], kh4[3]);
            }
        }

        // ---- online softmax (rows gid, gid+8; quad lanes share a row) ----
        float mx0 = -INFINITY, mx1 = -INFINITY;
        #pragma unroll
        for (int t = 0; t < 8; t++) {
            mx0 = fmaxf(mx0, fmaxf(sacc[t][0], sacc[t][1]));
            mx1 = fmaxf(mx1, fmaxf(sacc[t][2], sacc[t][3]));
        }
        #pragma unroll
        for (int off = 1; off < 4; off <<= 1) {
            mx0 = fmaxf(mx0, __shfl_xor_sync(0xffffffffu, mx0, off));
            mx1 = fmaxf(mx1, __shfl_xor_sync(0xffffffffu, mx1, off));
        }
        float mn0 = fmaxf(m_r[0], mx0), mn1 = fmaxf(m_r[1], mx1);
        float cr0 = __expf(m_r[0] - mn0), cr1 = __expf(m_r[1] - mn1);
        float rs0 = 0.0f, rs1 = 0.0f;
        #pragma unroll
        for (int t = 0; t < 8; t++) {
            sacc[t][0] = __expf(sacc[t][0] - mn0);
            sacc[t][1] = __expf(sacc[t][1] - mn0);
            sacc[t][2] = __expf(sacc[t][2] - mn1);
            sacc[t][3] = __expf(sacc[t][3] - mn1);
            rs0 += sacc[t][0] + sacc[t][1];
            rs1 += sacc[t][2] + sacc[t][3];
        }
        #pragma unroll
        for (int off = 1; off < 4; off <<= 1) {
            rs0 += __shfl_xor_sync(0xffffffffu, rs0, off);
            rs1 += __shfl_xor_sync(0xffffffffu, rs1, off);
        }
        l_r[0] = l_r[0] * cr0 + rs0;  m_r[0] = mn0;
        l_r[1] = l_r[1] * cr1 + rs1;  m_r[1] = mn1;
        #pragma unroll
        for (int t = 0; t < 8; t++) {
            oacc[t][0] *= cr0;  oacc[t][1] *= cr0;
            oacc[t][2] *= cr1;  oacc[t][3] *= cr1;
        }

        // ---- O += P V (P split in regs, V split via ldmatrix.trans) ----
        #pragma unroll
        for (int kc = 0; kc < 4; kc++) {
            uint32_t phi[4], plo[4];
            split2(sacc[2*kc][0],   sacc[2*kc][1],   phi[0], plo[0]);
            split2(sacc[2*kc][2],   sacc[2*kc][3],   phi[1], plo[1]);
            split2(sacc[2*kc+1][0], sacc[2*kc+1][1], phi[2], plo[2]);
            split2(sacc[2*kc+1][2], sacc[2*kc+1][3], phi[3], plo[3]);
            #pragma unroll
            for (int p = 0; p < 4; p++) {
                uint32_t off = (uint32_t)(kc * 16 + vk) * (ASTR * 2)
                             + (uint32_t)(p * 16 + vn8) * 2;
                uint32_t vh4[4], vl4[4];
                ldsm_x4_t(vh4, bVh + off);
                ldsm_x4_t(vl4, bVl + off);
                mma_bf16(oacc[2*p],   phi, vh4[0], vh4[1]);
                mma_bf16(oacc[2*p+1], phi, vh4[2], vh4[3]);
                mma_bf16(oacc[2*p],   phi, vl4[0], vl4[1]);
                mma_bf16(oacc[2*p+1], phi, vl4[2], vl4[3]);
                mma_bf16(oacc[2*p],   plo, vh4[0], vh4[1]);
                mma_bf16(oacc[2*p+1], plo, vh4[2], vh4[3]);
            }
        }
    }

    // ---- epilogue: normalize, split to bf16 hi/lo, write [B,T,D] ----
    const int gid = lane >> 2, tg2 = (lane & 3) * 2;
    const float inv0 = 1.0f / l_r[0], inv1 = 1.0f / l_r[1];
    const int b_ = bh >> 4, h = bh & 15;
    const int row0 = q0 + wid * 16 + gid;
    uint32_t* ahi32 = (uint32_t*)g_ahi;
    uint32_t* alo32 = (uint32_t*)g_alo;

    #pragma unroll
    for (int t = 0; t < 8; t++) {
        const int col = h * 64 + t * 8 + tg2;
        uint32_t hv, lv;
        split2(oacc[t][0] * inv0, oacc[t][1] * inv0, hv, lv);
        size_t e0 = (((size_t)(b_ * TT + row0)) * DM + col) >> 1;
        ahi32[e0] = hv;  alo32[e0] = lv;
        split2(oacc[t][2] * inv1, oacc[t][3] * inv1, hv, lv);
        size_t e1 = (((size_t)(b_ * TT + row0 + 8)) * DM + col) >> 1;
        ahi32[e1] = hv;  alo32[e1] = lv;
    }
}

// ---------------------------------------------------------------------------
extern "C" void kernel_launch(void* const* d_in, const int* in_sizes, int n_in,
                              void* d_out, int out_size)
{
    const float* x  = (const float*)d_in[0];
    const float* Wq = (const float*)d_in[1];
    const float* bq = (const float*)d_in[2];
    const float* Wk = (const float*)d_in[3];
    const float* bk = (const float*)d_in[4];
    const float* Wv = (const float*)d_in[5];
    const float* bv = (const float*)d_in[6];
    const float* Wo = (const float*)d_in[7];
    const float* bo = (const float*)d_in[8];
    float* out = (float*)d_out;

    cudaFuncSetAttribute(gemm_mma<0>, cudaFuncAttributeMaxDynamicSharedMemorySize, GSMEM);
    cudaFuncSetAttribute(gemm_mma<1>, cudaFuncAttributeMaxDynamicSharedMemorySize, GSMEM);
    cudaFuncSetAttribute(attn_mma_kernel, cudaFuncAttributeMaxDynamicSharedMemorySize, ASMEM);

    __nv_bfloat16 *xhi, *xlo, *ahi, *alo;
    cudaGetSymbolAddress((void**)&xhi, g_xhi);
    cudaGetSymbolAddress((void**)&xlo, g_xlo);
    cudaGetSymbolAddress((void**)&ahi, g_ahi);
    cudaGetSymbolAddress((void**)&alo, g_alo);

    // 0) split x and weights into bf16 hi/lo (vectorized) + trig table
    split2_kernel<<<(BT * DM / 2 + 255) / 256, 256>>>(x, xhi, xlo, BT * DM / 2);
    split_w2_kernel<<<(4 * DM * DM / 2 + 255) / 256, 256>>>(Wq, Wk, Wv, Wo);
    trig_kernel<<<(TT * 32 + 255) / 256, 256>>>();

    // 1) QKV projection: q,k -> fp32 [B,H,T,Dh]; v -> bf16 split
    dim3 g1(3072 / 128, BT / 128);
    gemm_mma<0><<<g1, 256, GSMEM>>>(xhi, xlo, bq, bk, bv, nullptr);

    // 2) RoPE apply + scale + bf16 split for q,k
    rope_apply_kernel<<<(BH * TT * 32) / 256, 256>>>();

    // 3) flash attention (mma.sync + cp.async) -> g_ahi/g_alo [B,T,D]
    dim3 g3(TT / 64, BH);
    attn_mma_kernel<<<g3, 128, ASMEM>>>();

    // 4) output projection -> d_out
    dim3 g4(DM / 128, BT / 128);
    gemm_mma<1><<<g4, 256, GSMEM>>>(ahi, alo, bo, nullptr, nullptr, out);
}